// round 9
// baseline (speedup 1.0000x reference)
#include <cuda_runtime.h>
#include <cuda_fp16.h>
#include <math.h>
#include <stdint.h>

#define Nq 8192
#define Kc 8192
#define Dd 512
#define Mq (2*Nq)

// ---- mma-argmin tiling ----
#define MT 128                 // queries per CTA
#define NTB 256                // codes per N-chunk (CTA tile 128x256)
#define NCB (Kc/NTB)           // 32
#define KCH 64                 // halfs per K chunk
#define KIT (Dd/KCH)           // 8
#define NCHUNKS (NCB*KIT)      // 256 pipeline steps
#define TILE_BYTES 16384       // one [128][64] half tile, swizzled
#define T_XH 0
#define T_CH 16384             // two codebook tiles follow the X tile
#define STAGE_BYTES 49152      // 48KB per stage (XH + CH0 + CH1)
#define NSTAGE 3
#define DSM_BYTES (NSTAGE*STAGE_BYTES + 1024)
#define CAP 512                // candidate slots per row
#define MARGIN 0.125f          // > 2x deterministic hi*hi error bound

// ---------------- device scratch ----------------
__device__ float  g_codebook[Kc*Dd];
__device__ __align__(16) __half t_chi[(size_t)Kc*Dd];
__device__ __align__(16) __half t_xhi[(size_t)Mq*Dd];
__device__ float  g_cbsq[Kc];
__device__ int    g_bi[Mq];
__device__ int    g_counts[2*Kc];
__device__ int    g_ccount[Mq];
__device__ int    g_cand[(size_t)Mq*CAP];
__device__ float  g_rowsums[Mq*2];

// ---------------- helpers ----------------
__device__ __forceinline__ uint32_t smem_u32(const void* p) {
    uint32_t a;
    asm("{ .reg .u64 t; cvta.to.shared.u64 t, %1; cvt.u32.u64 %0, t; }" : "=r"(a) : "l"(p));
    return a;
}
#define SWZ(o) ((o) ^ (((o) >> 3) & 0x70))
#define MBAR_INIT(a, c) asm volatile("mbarrier.init.shared.b64 [%0], %1;" :: "r"(a), "r"(c) : "memory")
#define MBAR_EXPECT(a, b) asm volatile("mbarrier.arrive.expect_tx.shared.b64 _, [%0], %1;" :: "r"(a), "r"(b) : "memory")
#define MBAR_WAIT(a, ph) do { \
    uint32_t _m = (a), _p = (ph), _d; \
    asm volatile("{ .reg .pred p; mbarrier.try_wait.parity.acquire.cta.shared::cta.b64 p, [%1], %2; selp.b32 %0,1,0,p; }" \
        : "=r"(_d) : "r"(_m), "r"(_p) : "memory"); \
    if (!_d) { asm volatile("{ .reg .pred P1; WL_%=: mbarrier.try_wait.parity.acquire.cta.shared::cta.b64 P1, [%0], %1, 0x989680; @P1 bra.uni WD_%=; bra.uni WL_%=; WD_%=: }" \
        :: "r"(_m), "r"(_p) : "memory"); } \
} while(0)
#define BULK_G2S(dst, src, bytes, mbar) \
    asm volatile("cp.async.bulk.shared::cluster.global.mbarrier::complete_tx::bytes [%0], [%1], %2, [%3];" \
        :: "r"(dst), "l"(src), "r"(bytes), "r"(mbar) : "memory")
#define LDSM_X4(r0,r1,r2,r3,a) \
    asm volatile("ldmatrix.sync.aligned.m8n8.x4.shared.b16 {%0,%1,%2,%3}, [%4];" \
        : "=r"(r0),"=r"(r1),"=r"(r2),"=r"(r3) : "r"(a))
#define MMA16816(d,a,b) \
    asm volatile("mma.sync.aligned.m16n8k16.row.col.f32.f16.f16.f32 " \
        "{%0,%1,%2,%3}, {%4,%5,%6,%7}, {%8,%9}, {%0,%1,%2,%3};" \
        : "+f"((d)[0]),"+f"((d)[1]),"+f"((d)[2]),"+f"((d)[3]) \
        : "r"((a)[0]),"r"((a)[1]),"r"((a)[2]),"r"((a)[3]), "r"((b)[0]),"r"((b)[1]))

// ---------------- reset (device globals persist across graph replays) ----
__global__ void reset_kernel() {
    int i = blockIdx.x * 256 + threadIdx.x;
    if (i < 2*Kc) g_counts[i] = 0;
    if (i < Mq)   g_ccount[i] = 0;
}

// ---------------- codebook GEMM (scalar, small) ----------------
__global__ __launch_bounds__(256) void codebook_gemm(
    const float* __restrict__ emb, const float* __restrict__ pw,
    const float* __restrict__ pb)
{
    __shared__ float Es[16][64];
    __shared__ float Ps[16][64];
    const int tid = threadIdx.x;
    const int tx = tid & 15, ty = tid >> 4;
    const int kb = blockIdx.x * 64, db = blockIdx.y * 64;
    const int lr = tid & 63, jq = tid >> 6;
    float acc[4][4];
    #pragma unroll
    for (int i = 0; i < 4; i++)
        #pragma unroll
        for (int j = 0; j < 4; j++) acc[i][j] = 0.f;
    for (int j0 = 0; j0 < Dd; j0 += 16) {
        float4 ve = *(const float4*)(emb + (size_t)(kb+lr)*Dd + j0 + jq*4);
        Es[jq*4+0][lr]=ve.x; Es[jq*4+1][lr]=ve.y; Es[jq*4+2][lr]=ve.z; Es[jq*4+3][lr]=ve.w;
        float4 vp = *(const float4*)(pw  + (size_t)(db+lr)*Dd + j0 + jq*4);
        Ps[jq*4+0][lr]=vp.x; Ps[jq*4+1][lr]=vp.y; Ps[jq*4+2][lr]=vp.z; Ps[jq*4+3][lr]=vp.w;
        __syncthreads();
        #pragma unroll
        for (int jj = 0; jj < 16; jj++) {
            float4 a = *(const float4*)&Es[jj][ty*4];
            float4 b = *(const float4*)&Ps[jj][tx*4];
            float ar[4] = {a.x,a.y,a.z,a.w};
            float br[4] = {b.x,b.y,b.z,b.w};
            #pragma unroll
            for (int i = 0; i < 4; i++)
                #pragma unroll
                for (int j = 0; j < 4; j++)
                    acc[i][j] = fmaf(ar[i], br[j], acc[i][j]);
        }
        __syncthreads();
    }
    #pragma unroll
    for (int j = 0; j < 4; j++) {
        float bias = pb[db + tx*4 + j];
        #pragma unroll
        for (int i = 0; i < 4; i++)
            g_codebook[(size_t)(kb + ty*4 + i)*Dd + db + tx*4 + j] = acc[i][j] + bias;
    }
}

// ---------------- cb_sq ----------------
__global__ void cbsq_kernel() {
    int row  = blockIdx.x * 8 + (threadIdx.x >> 5);
    int lane = threadIdx.x & 31;
    const float* c = g_codebook + (size_t)row * Dd;
    float s = 0.f;
    for (int d = lane*4; d < Dd; d += 128) {
        float4 v = *(const float4*)(c + d);
        s += v.x*v.x + v.y*v.y + v.z*v.z + v.w*v.w;
    }
    #pragma unroll
    for (int off = 16; off; off >>= 1) s += __shfl_down_sync(0xffffffffu, s, off);
    if (lane == 0) g_cbsq[row] = s;
}

// ---------------- fp16 hi split into pre-swizzled tiles ----------------
__device__ __forceinline__ uint4 pack_hi(const float* v) {
    __half2 a = __floats2half2_rn(v[0], v[1]);
    __half2 b = __floats2half2_rn(v[2], v[3]);
    __half2 c = __floats2half2_rn(v[4], v[5]);
    __half2 d = __floats2half2_rn(v[6], v[7]);
    uint4 r; r.x = *(uint32_t*)&a; r.y = *(uint32_t*)&b; r.z = *(uint32_t*)&c; r.w = *(uint32_t*)&d;
    return r;
}
__global__ void split_x_kernel(const float* __restrict__ X0, const float* __restrict__ X1) {
    size_t t = (size_t)blockIdx.x * 256 + threadIdx.x;   // segment id
    int m = (int)(t >> 6);
    int seg = (int)(t & 63);
    int kc = seg >> 3, s8 = seg & 7;
    const float* src = (m < Nq) ? (X0 + (size_t)m * Dd) : (X1 + (size_t)(m - Nq) * Dd);
    float v[8];
    float4 a = *(const float4*)(src + seg*8);
    float4 b = *(const float4*)(src + seg*8 + 4);
    v[0]=a.x; v[1]=a.y; v[2]=a.z; v[3]=a.w; v[4]=b.x; v[5]=b.y; v[6]=b.z; v[7]=b.w;
    size_t tile = (size_t)(m >> 7) * KIT + kc;
    uint32_t off = SWZ((uint32_t)((m & 127) * 128 + s8 * 16));
    *(uint4*)((char*)t_xhi + tile * TILE_BYTES + off) = pack_hi(v);
}
__global__ void split_c_kernel() {
    size_t t = (size_t)blockIdx.x * 256 + threadIdx.x;
    int m = (int)(t >> 6);
    int seg = (int)(t & 63);
    int kc = seg >> 3, s8 = seg & 7;
    const float* src = g_codebook + (size_t)m * Dd;
    float v[8];
    float4 a = *(const float4*)(src + seg*8);
    float4 b = *(const float4*)(src + seg*8 + 4);
    v[0]=a.x; v[1]=a.y; v[2]=a.z; v[3]=a.w; v[4]=b.x; v[5]=b.y; v[6]=b.z; v[7]=b.w;
    size_t tile = (size_t)(m >> 7) * KIT + kc;
    uint32_t off = SWZ((uint32_t)((m & 127) * 128 + s8 * 16));
    *(uint4*)((char*)t_chi + tile * TILE_BYTES + off) = pack_hi(v);
}

// ---------------- pass A: hi*hi MMA + margin candidate collection ---------
__global__ void __launch_bounds__(256, 1) argmin_mma() {
    extern __shared__ char dsm[];
    __shared__ float sCb[NTB];
    __shared__ __align__(8) unsigned long long mbar[NSTAGE];
    uint32_t sb = (smem_u32(dsm) + 1023) & ~1023u;
    uint32_t mb = smem_u32(mbar);

    const int tid = threadIdx.x, lane = tid & 31, wid = tid >> 5;
    const int wr = wid >> 2, wc = wid & 3;          // 2x4 warp grid, 64x64 per warp
    const int m0 = blockIdx.x * MT;
    const int r16 = lane & 15;
    const int c8  = (lane >> 4) * 8;

    float bd[8];
    #pragma unroll
    for (int s = 0; s < 8; s++) bd[s] = INFINITY;

    float acc[4][8][4];    // 128 regs

    const size_t xblk = (size_t)(m0 >> 7) * KIT;

    auto issue = [&](int cc) {
        const int nc = cc >> 3, kc = cc & 7;
        const uint32_t st = sb + (cc % NSTAGE) * STAGE_BYTES;
        const uint32_t mba = mb + (cc % NSTAGE) * 8;
        MBAR_EXPECT(mba, STAGE_BYTES);
        const char* xh  = (const char*)t_xhi + (xblk + kc) * TILE_BYTES;
        const char* ch0 = (const char*)t_chi + ((size_t)(2*nc)   * KIT + kc) * TILE_BYTES;
        const char* ch1 = (const char*)t_chi + ((size_t)(2*nc+1) * KIT + kc) * TILE_BYTES;
        BULK_G2S(st + T_XH,              __cvta_generic_to_global(xh),  TILE_BYTES, mba);
        BULK_G2S(st + T_CH,              __cvta_generic_to_global(ch0), TILE_BYTES, mba);
        BULK_G2S(st + T_CH + TILE_BYTES, __cvta_generic_to_global(ch1), TILE_BYTES, mba);
    };

    if (tid == 0) {
        #pragma unroll
        for (int s = 0; s < NSTAGE; s++) MBAR_INIT(mb + s*8, 1);
    }
    __syncthreads();
    if (tid == 0) { issue(0); issue(1); }

    for (int cc = 0; cc < NCHUNKS; cc++) {
        const int nc = cc >> 3, kc = cc & 7;
        const int s = cc % NSTAGE;

        MBAR_WAIT(mb + s*8, (cc/NSTAGE) & 1);
        __syncthreads();                 // all threads past chunk cc-1 compute
        if (tid == 0 && cc + 2 < NCHUNKS) issue(cc + 2);

        if (kc == 0) {
            sCb[tid] = g_cbsq[nc * NTB + tid];
            #pragma unroll
            for (int f = 0; f < 4; f++)
                #pragma unroll
                for (int n = 0; n < 8; n++)
                    #pragma unroll
                    for (int v = 0; v < 4; v++) acc[f][n][v] = 0.f;
        }

        const uint32_t tb = sb + s * STAGE_BYTES;
        #pragma unroll
        for (int kb = 0; kb < 4; kb++) {
            const uint32_t colb = (uint32_t)(kb * 16 + c8) * 2;
            uint32_t ah[4][4], bh[8][2];
            #pragma unroll
            for (int f = 0; f < 4; f++) {
                uint32_t off = SWZ((uint32_t)((wr * 64 + f * 16 + r16) * 128) + colb);
                LDSM_X4(ah[f][0], ah[f][1], ah[f][2], ah[f][3], tb + T_XH + off);
            }
            #pragma unroll
            for (int np = 0; np < 4; np++) {
                int brow = wc * 64 + np * 16 + r16;
                uint32_t off = (uint32_t)((brow >> 7) * TILE_BYTES)
                             + SWZ((uint32_t)((brow & 127) * 128) + colb);
                uint32_t q0, q1, q2, q3;
                LDSM_X4(q0, q1, q2, q3, tb + T_CH + off);
                bh[np*2][0] = q0; bh[np*2][1] = q2; bh[np*2+1][0] = q1; bh[np*2+1][1] = q3;
            }
            #pragma unroll
            for (int f = 0; f < 4; f++)
                #pragma unroll
                for (int n = 0; n < 8; n++)
                    MMA16816(acc[f][n], ah[f], bh[n]);
        }

        if (kc == KIT - 1) {
            // epilogue: approx dist = cbsq - 2*hi.hi ; push margin candidates
            #pragma unroll
            for (int f = 0; f < 4; f++) {
                int rowA = m0 + wr*64 + f*16 + (lane >> 2);
                int rowB = rowA + 8;
                #pragma unroll
                for (int n = 0; n < 8; n++) {
                    int lc = wc * 64 + n * 8 + (lane & 3) * 2;
                    int gc = nc * NTB + lc;
                    float cq0 = sCb[lc], cq1 = sCb[lc + 1];
                    float d0 = fmaf(-2.f, acc[f][n][0], cq0);
                    float d1 = fmaf(-2.f, acc[f][n][1], cq1);
                    float d2 = fmaf(-2.f, acc[f][n][2], cq0);
                    float d3 = fmaf(-2.f, acc[f][n][3], cq1);
                    if (d0 < bd[f] + MARGIN) {
                        int p = atomicAdd(&g_ccount[rowA], 1);
                        if (p < CAP) g_cand[(size_t)rowA*CAP + p] = gc;
                        if (d0 < bd[f]) bd[f] = d0;
                    }
                    if (d1 < bd[f] + MARGIN) {
                        int p = atomicAdd(&g_ccount[rowA], 1);
                        if (p < CAP) g_cand[(size_t)rowA*CAP + p] = gc + 1;
                        if (d1 < bd[f]) bd[f] = d1;
                    }
                    if (d2 < bd[f+4] + MARGIN) {
                        int p = atomicAdd(&g_ccount[rowB], 1);
                        if (p < CAP) g_cand[(size_t)rowB*CAP + p] = gc;
                        if (d2 < bd[f+4]) bd[f+4] = d2;
                    }
                    if (d3 < bd[f+4] + MARGIN) {
                        int p = atomicAdd(&g_ccount[rowB], 1);
                        if (p < CAP) g_cand[(size_t)rowB*CAP + p] = gc + 1;
                        if (d3 < bd[f+4]) bd[f+4] = d3;
                    }
                }
            }
        }
    }
}

// ---------------- exact fp32 rescore of candidates ----------------
__global__ void __launch_bounds__(256) rescore_kernel(
    const float* __restrict__ X0, const float* __restrict__ X1)
{
    const int m = blockIdx.x;
    const int tid = threadIdx.x, lane = tid & 31, w = tid >> 5;  // 8 warps
    __shared__ float sx[Dd];
    __shared__ float wbD[8];
    __shared__ int   wbK[8];

    const float* x = (m < Nq) ? (X0 + (size_t)m*Dd) : (X1 + (size_t)(m-Nq)*Dd);
    for (int i = tid; i < Dd; i += 256) sx[i] = x[i];
    __syncthreads();

    int cnt = g_ccount[m]; if (cnt > CAP) cnt = CAP;
    float best = INFINITY; int bk = 0x7fffffff;
    for (int c = w; c < cnt; c += 8) {
        int k = g_cand[(size_t)m*CAP + c];
        const float* cb = g_codebook + (size_t)k * Dd;
        float s = 0.f;
        for (int j = lane; j < Dd; j += 32) s = fmaf(sx[j], cb[j], s);
        #pragma unroll
        for (int o = 16; o; o >>= 1) s += __shfl_xor_sync(0xffffffffu, s, o);
        float d = fmaf(-2.f, s, g_cbsq[k]);
        if (d < best || (d == best && k < bk)) { best = d; bk = k; }
    }
    if (lane == 0) { wbD[w] = best; wbK[w] = bk; }
    __syncthreads();
    if (tid == 0) {
        float B = wbD[0]; int K = wbK[0];
        #pragma unroll
        for (int i = 1; i < 8; i++)
            if (wbD[i] < B || (wbD[i] == B && wbK[i] < K)) { B = wbD[i]; K = wbK[i]; }
        g_bi[m] = K;
    }
}

// ---------------- gather + per-row MSE partials ----------------
__global__ void gather_kernel(const float* __restrict__ X0,
                              const float* __restrict__ X1,
                              float* __restrict__ out)
{
    const int m = blockIdx.x;
    const int tid = threadIdx.x;   // 128
    __shared__ float wsum[4][2];

    const int idx = g_bi[m];
    if (tid == 0) {
        int src = (m < Nq) ? 0 : 1;
        atomicAdd(&g_counts[src*Kc + idx], 1);
    }
    const float* q = g_codebook + (size_t)idx * Dd;
    const float *x, *o; float* op;
    if (m < Nq) { x = X0 + (size_t)m*Dd; o = X1 + (size_t)m*Dd; op = out + (size_t)m*Dd; }
    else { int mr = m - Nq;
           x = X1 + (size_t)mr*Dd; o = X0 + (size_t)mr*Dd; op = out + (size_t)(Nq+mr)*Dd; }

    float4 qv = *(const float4*)(q + tid*4);
    float4 xv = *(const float4*)(x + tid*4);
    float4 ov = *(const float4*)(o + tid*4);
    float dx0 = qv.x - xv.x, dx1 = qv.y - xv.y, dx2 = qv.z - xv.z, dx3 = qv.w - xv.w;
    float4 w = {xv.x + dx0, xv.y + dx1, xv.z + dx2, xv.w + dx3};
    *(float4*)(op + tid*4) = w;

    float sA = dx0*dx0 + dx1*dx1 + dx2*dx2 + dx3*dx3;
    float e0 = qv.x - ov.x, e1 = qv.y - ov.y, e2 = qv.z - ov.z, e3 = qv.w - ov.w;
    float sB = e0*e0 + e1*e1 + e2*e2 + e3*e3;
    #pragma unroll
    for (int off = 16; off; off >>= 1) {
        sA += __shfl_down_sync(0xffffffffu, sA, off);
        sB += __shfl_down_sync(0xffffffffu, sB, off);
    }
    int warp = tid >> 5, lane = tid & 31;
    if (lane == 0) { wsum[warp][0] = sA; wsum[warp][1] = sB; }
    __syncthreads();
    if (tid == 0) {
        g_rowsums[2*m]   = wsum[0][0] + wsum[1][0] + wsum[2][0] + wsum[3][0];
        g_rowsums[2*m+1] = wsum[0][1] + wsum[1][1] + wsum[2][1] + wsum[3][1];
    }
}

// ---------------- losses ----------------
__global__ void loss_kernel(float* __restrict__ out) {
    const int t = threadIdx.x;
    __shared__ double red[4][256];
    double es = 0, csr = 0, er = 0, crs = 0;
    for (int m = t; m < Nq; m += 256)      { es  += (double)g_rowsums[2*m]; csr += (double)g_rowsums[2*m+1]; }
    for (int m = Nq + t; m < Mq; m += 256) { er  += (double)g_rowsums[2*m]; crs += (double)g_rowsums[2*m+1]; }
    red[0][t]=es; red[1][t]=csr; red[2][t]=er; red[3][t]=crs;
    __syncthreads();
    for (int off = 128; off; off >>= 1) {
        if (t < off) {
            red[0][t]+=red[0][t+off]; red[1][t]+=red[1][t+off];
            red[2][t]+=red[2][t+off]; red[3][t]+=red[3][t+off];
        }
        __syncthreads();
    }
    if (t == 0) {
        const double nd = (double)Nq * (double)Dd;
        double Es = red[0][0]/nd, Csr = red[1][0]/nd, Er = red[2][0]/nd, Crs = red[3][0]/nd;
        out[(size_t)2*Nq*Dd + 0] = (float)(0.5 * Es);
        double fwd = Er + Es + 0.5*Crs + 0.5*Csr;
        out[(size_t)2*Nq*Dd + 1] = (float)(0.5*Er + 0.25*fwd);
    }
}

// ---------------- perplexity ----------------
__global__ void perp_kernel(float* __restrict__ out) {
    const int src = blockIdx.x;
    const int t = threadIdx.x;
    __shared__ float red[256];
    float h = 0.f;
    for (int k = t; k < Kc; k += 256) {
        float p = (float)g_counts[src*Kc + k] * (1.0f/(float)Nq);
        h += p * logf(p + 1e-10f);
    }
    red[t] = h;
    __syncthreads();
    for (int off = 128; off; off >>= 1) {
        if (t < off) red[t] += red[t+off];
        __syncthreads();
    }
    if (t == 0) out[(size_t)2*Nq*Dd + 2 + src] = expf(-red[0]);
}

// ---------------- launcher ----------------
extern "C" void kernel_launch(void* const* d_in, const int* in_sizes, int n_in,
                              void* d_out, int out_size)
{
    const float* scRNA = (const float*)d_in[0];
    const float* ribo  = (const float*)d_in[1];
    const float* emb   = (const float*)d_in[2];
    const float* pw    = (const float*)d_in[3];
    const float* pb    = (const float*)d_in[4];
    float* out = (float*)d_out;

    cudaFuncSetAttribute(argmin_mma, cudaFuncAttributeMaxDynamicSharedMemorySize, DSM_BYTES);

    reset_kernel<<<(2*Kc + 255)/256, 256>>>();
    codebook_gemm<<<dim3(Kc/64, Dd/64), 256>>>(emb, pw, pb);
    cbsq_kernel<<<Kc/8, 256>>>();
    split_c_kernel<<<(int)(((size_t)Kc*Dd/8)/256), 256>>>();
    split_x_kernel<<<(int)(((size_t)Mq*Dd/8)/256), 256>>>(scRNA, ribo);
    argmin_mma<<<Mq/MT, 256, DSM_BYTES>>>();
    rescore_kernel<<<Mq, 256>>>(scRNA, ribo);
    gather_kernel<<<Mq, 128>>>(scRNA, ribo, out);
    loss_kernel<<<1, 256>>>(out);
    perp_kernel<<<2, 256>>>(out);
}

// round 11
// speedup vs baseline: 1.1334x; 1.1334x over previous
#include <cuda_runtime.h>
#include <cuda_fp16.h>
#include <math.h>
#include <stdint.h>

#define Nq 8192
#define Kc 8192
#define Dd 512
#define Mq (2*Nq)

// ---- mma-argmin tiling ----
#define MT 128                 // queries per CTA
#define NTB 256                // codes per N-chunk (CTA tile 128x256)
#define NCB (Kc/NTB)           // 32
#define KCH 64                 // halfs per K chunk
#define KIT (Dd/KCH)           // 8
#define NCHUNKS (NCB*KIT)      // 256 pipeline steps
#define TILE_BYTES 16384       // one [128][64] half tile, swizzled
#define T_XH 0
#define T_CH 16384             // two codebook tiles follow the X tile
#define STAGE_BYTES 49152      // 48KB per stage (XH + CH0 + CH1)
#define NSTAGE 3
#define DSM_BYTES (NSTAGE*STAGE_BYTES + 1024)
#define CAP 512                // candidate slots per row
#define MARGIN 0.125f          // >= 2x deterministic hi*hi error bound

// ---------------- device scratch ----------------
__device__ float  g_codebook[Kc*Dd];
__device__ __align__(16) __half t_chi[(size_t)Kc*Dd];
__device__ __align__(16) __half t_xhi[(size_t)Mq*Dd];
__device__ float  g_cbsq[Kc];
__device__ int    g_bi[Mq];
__device__ int    g_counts[2*Kc];
__device__ int    g_ccount[Mq];
__device__ int    g_candk[(size_t)Mq*CAP];
__device__ float  g_candd[(size_t)Mq*CAP];
__device__ float  g_amin[Mq];
__device__ float  g_rowsums[Mq*2];

// ---------------- helpers ----------------
__device__ __forceinline__ uint32_t smem_u32(const void* p) {
    uint32_t a;
    asm("{ .reg .u64 t; cvta.to.shared.u64 t, %1; cvt.u32.u64 %0, t; }" : "=r"(a) : "l"(p));
    return a;
}
#define SWZ(o) ((o) ^ (((o) >> 3) & 0x70))
#define MBAR_INIT(a, c) asm volatile("mbarrier.init.shared.b64 [%0], %1;" :: "r"(a), "r"(c) : "memory")
#define MBAR_EXPECT(a, b) asm volatile("mbarrier.arrive.expect_tx.shared.b64 _, [%0], %1;" :: "r"(a), "r"(b) : "memory")
#define MBAR_WAIT(a, ph) do { \
    uint32_t _m = (a), _p = (ph), _d; \
    asm volatile("{ .reg .pred p; mbarrier.try_wait.parity.acquire.cta.shared::cta.b64 p, [%1], %2; selp.b32 %0,1,0,p; }" \
        : "=r"(_d) : "r"(_m), "r"(_p) : "memory"); \
    if (!_d) { asm volatile("{ .reg .pred P1; WL_%=: mbarrier.try_wait.parity.acquire.cta.shared::cta.b64 P1, [%0], %1, 0x989680; @P1 bra.uni WD_%=; bra.uni WL_%=; WD_%=: }" \
        :: "r"(_m), "r"(_p) : "memory"); } \
} while(0)
#define BULK_G2S(dst, src, bytes, mbar) \
    asm volatile("cp.async.bulk.shared::cluster.global.mbarrier::complete_tx::bytes [%0], [%1], %2, [%3];" \
        :: "r"(dst), "l"(src), "r"(bytes), "r"(mbar) : "memory")
#define LDSM_X4(r0,r1,r2,r3,a) \
    asm volatile("ldmatrix.sync.aligned.m8n8.x4.shared.b16 {%0,%1,%2,%3}, [%4];" \
        : "=r"(r0),"=r"(r1),"=r"(r2),"=r"(r3) : "r"(a))
#define MMA16816(d,a,b) \
    asm volatile("mma.sync.aligned.m16n8k16.row.col.f32.f16.f16.f32 " \
        "{%0,%1,%2,%3}, {%4,%5,%6,%7}, {%8,%9}, {%0,%1,%2,%3};" \
        : "+f"((d)[0]),"+f"((d)[1]),"+f"((d)[2]),"+f"((d)[3]) \
        : "r"((a)[0]),"r"((a)[1]),"r"((a)[2]),"r"((a)[3]), "r"((b)[0]),"r"((b)[1]))

// ---------------- reset (device globals persist across graph replays) ----
__global__ void reset_kernel() {
    int i = blockIdx.x * 256 + threadIdx.x;
    if (i < 2*Kc) g_counts[i] = 0;
    if (i < Mq)   g_ccount[i] = 0;
}

// ---------------- codebook GEMM (scalar, small) ----------------
__global__ __launch_bounds__(256) void codebook_gemm(
    const float* __restrict__ emb, const float* __restrict__ pw,
    const float* __restrict__ pb)
{
    __shared__ float Es[16][64];
    __shared__ float Ps[16][64];
    const int tid = threadIdx.x;
    const int tx = tid & 15, ty = tid >> 4;
    const int kb = blockIdx.x * 64, db = blockIdx.y * 64;
    const int lr = tid & 63, jq = tid >> 6;
    float acc[4][4];
    #pragma unroll
    for (int i = 0; i < 4; i++)
        #pragma unroll
        for (int j = 0; j < 4; j++) acc[i][j] = 0.f;
    for (int j0 = 0; j0 < Dd; j0 += 16) {
        float4 ve = *(const float4*)(emb + (size_t)(kb+lr)*Dd + j0 + jq*4);
        Es[jq*4+0][lr]=ve.x; Es[jq*4+1][lr]=ve.y; Es[jq*4+2][lr]=ve.z; Es[jq*4+3][lr]=ve.w;
        float4 vp = *(const float4*)(pw  + (size_t)(db+lr)*Dd + j0 + jq*4);
        Ps[jq*4+0][lr]=vp.x; Ps[jq*4+1][lr]=vp.y; Ps[jq*4+2][lr]=vp.z; Ps[jq*4+3][lr]=vp.w;
        __syncthreads();
        #pragma unroll
        for (int jj = 0; jj < 16; jj++) {
            float4 a = *(const float4*)&Es[jj][ty*4];
            float4 b = *(const float4*)&Ps[jj][tx*4];
            float ar[4] = {a.x,a.y,a.z,a.w};
            float br[4] = {b.x,b.y,b.z,b.w};
            #pragma unroll
            for (int i = 0; i < 4; i++)
                #pragma unroll
                for (int j = 0; j < 4; j++)
                    acc[i][j] = fmaf(ar[i], br[j], acc[i][j]);
        }
        __syncthreads();
    }
    #pragma unroll
    for (int j = 0; j < 4; j++) {
        float bias = pb[db + tx*4 + j];
        #pragma unroll
        for (int i = 0; i < 4; i++)
            g_codebook[(size_t)(kb + ty*4 + i)*Dd + db + tx*4 + j] = acc[i][j] + bias;
    }
}

// ---------------- cb_sq ----------------
__global__ void cbsq_kernel() {
    int row  = blockIdx.x * 8 + (threadIdx.x >> 5);
    int lane = threadIdx.x & 31;
    const float* c = g_codebook + (size_t)row * Dd;
    float s = 0.f;
    for (int d = lane*4; d < Dd; d += 128) {
        float4 v = *(const float4*)(c + d);
        s += v.x*v.x + v.y*v.y + v.z*v.z + v.w*v.w;
    }
    #pragma unroll
    for (int off = 16; off; off >>= 1) s += __shfl_down_sync(0xffffffffu, s, off);
    if (lane == 0) g_cbsq[row] = s;
}

// ---------------- fp16 hi split into pre-swizzled tiles ----------------
__device__ __forceinline__ uint4 pack_hi(const float* v) {
    __half2 a = __floats2half2_rn(v[0], v[1]);
    __half2 b = __floats2half2_rn(v[2], v[3]);
    __half2 c = __floats2half2_rn(v[4], v[5]);
    __half2 d = __floats2half2_rn(v[6], v[7]);
    uint4 r; r.x = *(uint32_t*)&a; r.y = *(uint32_t*)&b; r.z = *(uint32_t*)&c; r.w = *(uint32_t*)&d;
    return r;
}
__global__ void split_x_kernel(const float* __restrict__ X0, const float* __restrict__ X1) {
    size_t t = (size_t)blockIdx.x * 256 + threadIdx.x;   // segment id
    int m = (int)(t >> 6);
    int seg = (int)(t & 63);
    int kc = seg >> 3, s8 = seg & 7;
    const float* src = (m < Nq) ? (X0 + (size_t)m * Dd) : (X1 + (size_t)(m - Nq) * Dd);
    float v[8];
    float4 a = *(const float4*)(src + seg*8);
    float4 b = *(const float4*)(src + seg*8 + 4);
    v[0]=a.x; v[1]=a.y; v[2]=a.z; v[3]=a.w; v[4]=b.x; v[5]=b.y; v[6]=b.z; v[7]=b.w;
    size_t tile = (size_t)(m >> 7) * KIT + kc;
    uint32_t off = SWZ((uint32_t)((m & 127) * 128 + s8 * 16));
    *(uint4*)((char*)t_xhi + tile * TILE_BYTES + off) = pack_hi(v);
}
__global__ void split_c_kernel() {
    size_t t = (size_t)blockIdx.x * 256 + threadIdx.x;
    int m = (int)(t >> 6);
    int seg = (int)(t & 63);
    int kc = seg >> 3, s8 = seg & 7;
    const float* src = g_codebook + (size_t)m * Dd;
    float v[8];
    float4 a = *(const float4*)(src + seg*8);
    float4 b = *(const float4*)(src + seg*8 + 4);
    v[0]=a.x; v[1]=a.y; v[2]=a.z; v[3]=a.w; v[4]=b.x; v[5]=b.y; v[6]=b.z; v[7]=b.w;
    size_t tile = (size_t)(m >> 7) * KIT + kc;
    uint32_t off = SWZ((uint32_t)((m & 127) * 128 + s8 * 16));
    *(uint4*)((char*)t_chi + tile * TILE_BYTES + off) = pack_hi(v);
}

// ---------------- pass A: hi*hi MMA + margin candidate collection ---------
__global__ void __launch_bounds__(256, 1) argmin_mma() {
    extern __shared__ char dsm[];
    __shared__ float sCb[NTB];
    __shared__ float sD[MT][4];
    __shared__ __align__(8) unsigned long long mbar[NSTAGE];
    uint32_t sb = (smem_u32(dsm) + 1023) & ~1023u;
    uint32_t mb = smem_u32(mbar);

    const int tid = threadIdx.x, lane = tid & 31, wid = tid >> 5;
    const int wr = wid >> 2, wc = wid & 3;          // 2x4 warp grid, 64x64 per warp
    const int m0 = blockIdx.x * MT;
    const int r16 = lane & 15;
    const int c8  = (lane >> 4) * 8;

    float bd[8];
    #pragma unroll
    for (int s = 0; s < 8; s++) bd[s] = INFINITY;

    float acc[4][8][4];

    const size_t xblk = (size_t)(m0 >> 7) * KIT;

    auto issue = [&](int cc) {
        const int nc = cc >> 3, kc = cc & 7;
        const uint32_t st = sb + (cc % NSTAGE) * STAGE_BYTES;
        const uint32_t mba = mb + (cc % NSTAGE) * 8;
        MBAR_EXPECT(mba, STAGE_BYTES);
        const char* xh  = (const char*)t_xhi + (xblk + kc) * TILE_BYTES;
        const char* ch0 = (const char*)t_chi + ((size_t)(2*nc)   * KIT + kc) * TILE_BYTES;
        const char* ch1 = (const char*)t_chi + ((size_t)(2*nc+1) * KIT + kc) * TILE_BYTES;
        BULK_G2S(st + T_XH,              __cvta_generic_to_global(xh),  TILE_BYTES, mba);
        BULK_G2S(st + T_CH,              __cvta_generic_to_global(ch0), TILE_BYTES, mba);
        BULK_G2S(st + T_CH + TILE_BYTES, __cvta_generic_to_global(ch1), TILE_BYTES, mba);
    };

    if (tid == 0) {
        #pragma unroll
        for (int s = 0; s < NSTAGE; s++) MBAR_INIT(mb + s*8, 1);
    }
    __syncthreads();
    if (tid == 0) { issue(0); issue(1); }

    for (int cc = 0; cc < NCHUNKS; cc++) {
        const int nc = cc >> 3, kc = cc & 7;
        const int s = cc % NSTAGE;

        MBAR_WAIT(mb + s*8, (cc/NSTAGE) & 1);
        __syncthreads();
        if (tid == 0 && cc + 2 < NCHUNKS) issue(cc + 2);

        if (kc == 0) {
            sCb[tid] = g_cbsq[nc * NTB + tid];
            #pragma unroll
            for (int f = 0; f < 4; f++)
                #pragma unroll
                for (int n = 0; n < 8; n++)
                    #pragma unroll
                    for (int v = 0; v < 4; v++) acc[f][n][v] = 0.f;
        }

        const uint32_t tb = sb + s * STAGE_BYTES;
        #pragma unroll
        for (int kb = 0; kb < 4; kb++) {
            const uint32_t colb = (uint32_t)(kb * 16 + c8) * 2;
            uint32_t ah[4][4], bh[8][2];
            #pragma unroll
            for (int f = 0; f < 4; f++) {
                uint32_t off = SWZ((uint32_t)((wr * 64 + f * 16 + r16) * 128) + colb);
                LDSM_X4(ah[f][0], ah[f][1], ah[f][2], ah[f][3], tb + T_XH + off);
            }
            #pragma unroll
            for (int np = 0; np < 4; np++) {
                int brow = wc * 64 + np * 16 + r16;
                uint32_t off = (uint32_t)((brow >> 7) * TILE_BYTES)
                             + SWZ((uint32_t)((brow & 127) * 128) + colb);
                uint32_t q0, q1, q2, q3;
                LDSM_X4(q0, q1, q2, q3, tb + T_CH + off);
                bh[np*2][0] = q0; bh[np*2][1] = q2; bh[np*2+1][0] = q1; bh[np*2+1][1] = q3;
            }
            #pragma unroll
            for (int f = 0; f < 4; f++)
                #pragma unroll
                for (int n = 0; n < 8; n++)
                    MMA16816(acc[f][n], ah[f], bh[n]);
        }

        if (kc == KIT - 1) {
            // epilogue: approx dist = cbsq - 2*hi.hi ; push (k, d) candidates
            #pragma unroll
            for (int f = 0; f < 4; f++) {
                int rowA = m0 + wr*64 + f*16 + (lane >> 2);
                int rowB = rowA + 8;
                #pragma unroll
                for (int n = 0; n < 8; n++) {
                    int lc = wc * 64 + n * 8 + (lane & 3) * 2;
                    int gc = nc * NTB + lc;
                    float cq0 = sCb[lc], cq1 = sCb[lc + 1];
                    float d0 = fmaf(-2.f, acc[f][n][0], cq0);
                    float d1 = fmaf(-2.f, acc[f][n][1], cq1);
                    float d2 = fmaf(-2.f, acc[f][n][2], cq0);
                    float d3 = fmaf(-2.f, acc[f][n][3], cq1);
                    if (d0 < bd[f] + MARGIN) {
                        int p = atomicAdd(&g_ccount[rowA], 1);
                        if (p < CAP) { g_candk[(size_t)rowA*CAP + p] = gc;   g_candd[(size_t)rowA*CAP + p] = d0; }
                        if (d0 < bd[f]) bd[f] = d0;
                    }
                    if (d1 < bd[f] + MARGIN) {
                        int p = atomicAdd(&g_ccount[rowA], 1);
                        if (p < CAP) { g_candk[(size_t)rowA*CAP + p] = gc+1; g_candd[(size_t)rowA*CAP + p] = d1; }
                        if (d1 < bd[f]) bd[f] = d1;
                    }
                    if (d2 < bd[f+4] + MARGIN) {
                        int p = atomicAdd(&g_ccount[rowB], 1);
                        if (p < CAP) { g_candk[(size_t)rowB*CAP + p] = gc;   g_candd[(size_t)rowB*CAP + p] = d2; }
                        if (d2 < bd[f+4]) bd[f+4] = d2;
                    }
                    if (d3 < bd[f+4] + MARGIN) {
                        int p = atomicAdd(&g_ccount[rowB], 1);
                        if (p < CAP) { g_candk[(size_t)rowB*CAP + p] = gc+1; g_candd[(size_t)rowB*CAP + p] = d3; }
                        if (d3 < bd[f+4]) bd[f+4] = d3;
                    }
                }
            }
        }
    }

    // final per-row approx minimum (for candidate filtering)
    #pragma unroll
    for (int s = 0; s < 8; s++) {
        #pragma unroll
        for (int x = 1; x <= 2; x <<= 1)
            bd[s] = fminf(bd[s], __shfl_xor_sync(0xffffffffu, bd[s], x));
        int row = wr * 64 + (s & 3) * 16 + (lane >> 2) + ((s >= 4) ? 8 : 0);
        if ((lane & 3) == 0) sD[row][wc] = bd[s];
    }
    __syncthreads();
    if (tid < MT) {
        float a = fminf(fminf(sD[tid][0], sD[tid][1]), fminf(sD[tid][2], sD[tid][3]));
        g_amin[m0 + tid] = a;
    }
}

// ---------------- filtered exact fp32 rescore ----------------
__global__ void __launch_bounds__(128) rescore_kernel(
    const float* __restrict__ X0, const float* __restrict__ X1)
{
    const int m = blockIdx.x;
    const int tid = threadIdx.x, lane = tid & 31, w = tid >> 5;  // 4 warps
    __shared__ float sx[Dd];
    __shared__ float wbD[4];
    __shared__ int   wbK[4];

    const float* x = (m < Nq) ? (X0 + (size_t)m*Dd) : (X1 + (size_t)(m-Nq)*Dd);
    for (int i = tid; i < Dd; i += 128) sx[i] = x[i];
    __syncthreads();

    const float thr = g_amin[m] + MARGIN;
    int cnt = g_ccount[m]; if (cnt > CAP) cnt = CAP;
    float best = INFINITY; int bk = 0x7fffffff;
    for (int c = w; c < cnt; c += 4) {
        float da = g_candd[(size_t)m*CAP + c];
        if (da > thr) continue;                       // filtered out
        int k = g_candk[(size_t)m*CAP + c];
        const float* cb = g_codebook + (size_t)k * Dd;
        float s = 0.f;
        for (int j = lane; j < Dd; j += 32) s = fmaf(sx[j], cb[j], s);
        #pragma unroll
        for (int o = 16; o; o >>= 1) s += __shfl_xor_sync(0xffffffffu, s, o);
        float d = fmaf(-2.f, s, g_cbsq[k]);
        if (d < best || (d == best && k < bk)) { best = d; bk = k; }
    }
    if (lane == 0) { wbD[w] = best; wbK[w] = bk; }
    __syncthreads();
    if (tid == 0) {
        float B = wbD[0]; int K = wbK[0];
        #pragma unroll
        for (int i = 1; i < 4; i++)
            if (wbD[i] < B || (wbD[i] == B && wbK[i] < K)) { B = wbD[i]; K = wbK[i]; }
        g_bi[m] = K;
    }
}

// ---------------- gather + per-row MSE partials ----------------
__global__ void gather_kernel(const float* __restrict__ X0,
                              const float* __restrict__ X1,
                              float* __restrict__ out)
{
    const int m = blockIdx.x;
    const int tid = threadIdx.x;   // 128
    __shared__ float wsum[4][2];

    const int idx = g_bi[m];
    if (tid == 0) {
        int src = (m < Nq) ? 0 : 1;
        atomicAdd(&g_counts[src*Kc + idx], 1);
    }
    const float* q = g_codebook + (size_t)idx * Dd;
    const float *x, *o; float* op;
    if (m < Nq) { x = X0 + (size_t)m*Dd; o = X1 + (size_t)m*Dd; op = out + (size_t)m*Dd; }
    else { int mr = m - Nq;
           x = X1 + (size_t)mr*Dd; o = X0 + (size_t)mr*Dd; op = out + (size_t)(Nq+mr)*Dd; }

    float4 qv = *(const float4*)(q + tid*4);
    float4 xv = *(const float4*)(x + tid*4);
    float4 ov = *(const float4*)(o + tid*4);
    float dx0 = qv.x - xv.x, dx1 = qv.y - xv.y, dx2 = qv.z - xv.z, dx3 = qv.w - xv.w;
    float4 w = {xv.x + dx0, xv.y + dx1, xv.z + dx2, xv.w + dx3};
    *(float4*)(op + tid*4) = w;

    float sA = dx0*dx0 + dx1*dx1 + dx2*dx2 + dx3*dx3;
    float e0 = qv.x - ov.x, e1 = qv.y - ov.y, e2 = qv.z - ov.z, e3 = qv.w - ov.w;
    float sB = e0*e0 + e1*e1 + e2*e2 + e3*e3;
    #pragma unroll
    for (int off = 16; off; off >>= 1) {
        sA += __shfl_down_sync(0xffffffffu, sA, off);
        sB += __shfl_down_sync(0xffffffffu, sB, off);
    }
    int warp = tid >> 5, lane = tid & 31;
    if (lane == 0) { wsum[warp][0] = sA; wsum[warp][1] = sB; }
    __syncthreads();
    if (tid == 0) {
        g_rowsums[2*m]   = wsum[0][0] + wsum[1][0] + wsum[2][0] + wsum[3][0];
        g_rowsums[2*m+1] = wsum[0][1] + wsum[1][1] + wsum[2][1] + wsum[3][1];
    }
}

// ---------------- losses ----------------
__global__ void loss_kernel(float* __restrict__ out) {
    const int t = threadIdx.x;
    __shared__ double red[4][256];
    double es = 0, csr = 0, er = 0, crs = 0;
    for (int m = t; m < Nq; m += 256)      { es  += (double)g_rowsums[2*m]; csr += (double)g_rowsums[2*m+1]; }
    for (int m = Nq + t; m < Mq; m += 256) { er  += (double)g_rowsums[2*m]; crs += (double)g_rowsums[2*m+1]; }
    red[0][t]=es; red[1][t]=csr; red[2][t]=er; red[3][t]=crs;
    __syncthreads();
    for (int off = 128; off; off >>= 1) {
        if (t < off) {
            red[0][t]+=red[0][t+off]; red[1][t]+=red[1][t+off];
            red[2][t]+=red[2][t+off]; red[3][t]+=red[3][t+off];
        }
        __syncthreads();
    }
    if (t == 0) {
        const double nd = (double)Nq * (double)Dd;
        double Es = red[0][0]/nd, Csr = red[1][0]/nd, Er = red[2][0]/nd, Crs = red[3][0]/nd;
        out[(size_t)2*Nq*Dd + 0] = (float)(0.5 * Es);
        double fwd = Er + Es + 0.5*Crs + 0.5*Csr;
        out[(size_t)2*Nq*Dd + 1] = (float)(0.5*Er + 0.25*fwd);
    }
}

// ---------------- perplexity ----------------
__global__ void perp_kernel(float* __restrict__ out) {
    const int src = blockIdx.x;
    const int t = threadIdx.x;
    __shared__ float red[256];
    float h = 0.f;
    for (int k = t; k < Kc; k += 256) {
        float p = (float)g_counts[src*Kc + k] * (1.0f/(float)Nq);
        h += p * logf(p + 1e-10f);
    }
    red[t] = h;
    __syncthreads();
    for (int off = 128; off; off >>= 1) {
        if (t < off) red[t] += red[t+off];
        __syncthreads();
    }
    if (t == 0) out[(size_t)2*Nq*Dd + 2 + src] = expf(-red[0]);
}

// ---------------- launcher ----------------
extern "C" void kernel_launch(void* const* d_in, const int* in_sizes, int n_in,
                              void* d_out, int out_size)
{
    const float* scRNA = (const float*)d_in[0];
    const float* ribo  = (const float*)d_in[1];
    const float* emb   = (const float*)d_in[2];
    const float* pw    = (const float*)d_in[3];
    const float* pb    = (const float*)d_in[4];
    float* out = (float*)d_out;

    cudaFuncSetAttribute(argmin_mma, cudaFuncAttributeMaxDynamicSharedMemorySize, DSM_BYTES);

    reset_kernel<<<(2*Kc + 255)/256, 256>>>();
    codebook_gemm<<<dim3(Kc/64, Dd/64), 256>>>(emb, pw, pb);
    cbsq_kernel<<<Kc/8, 256>>>();
    split_c_kernel<<<(int)(((size_t)Kc*Dd/8)/256), 256>>>();
    split_x_kernel<<<(int)(((size_t)Mq*Dd/8)/256), 256>>>(scRNA, ribo);
    argmin_mma<<<Mq/MT, 256, DSM_BYTES>>>();
    rescore_kernel<<<Mq, 128>>>(scRNA, ribo);
    gather_kernel<<<Mq, 128>>>(scRNA, ribo, out);
    loss_kernel<<<1, 256>>>(out);
    perp_kernel<<<2, 256>>>(out);
}

// round 12
// speedup vs baseline: 1.1557x; 1.0196x over previous
#include <cuda_runtime.h>
#include <cuda_fp16.h>
#include <math.h>
#include <stdint.h>

#define Nq 8192
#define Kc 8192
#define Dd 512
#define Mq (2*Nq)

// ---- mma-argmin tiling ----
#define MT 128                 // queries per CTA
#define NTB 256                // codes per N-chunk (CTA tile 128x256)
#define NCB (Kc/NTB)           // 32
#define KCH 64                 // halfs per K chunk
#define KIT (Dd/KCH)           // 8
#define NCHUNKS (NCB*KIT)      // 256 pipeline steps
#define TILE_BYTES 16384       // one [128][64] half tile, swizzled
#define CSTAGE_BYTES 32768     // 2 codebook tiles per chunk
#define XRES_BYTES (KIT*TILE_BYTES)   // 128KB resident X
#define DSM_BYTES (1024 + 2*CSTAGE_BYTES + XRES_BYTES)
#define CAP 512                // candidate slots per row
#define MARGIN 0.125f          // >= 2x deterministic hi*hi error bound

// ---------------- device scratch ----------------
__device__ float  g_codebook[Kc*Dd];
__device__ __align__(16) __half t_chi[(size_t)Kc*Dd];
__device__ __align__(16) __half t_xhi[(size_t)Mq*Dd];
__device__ float  g_cbsq[Kc];
__device__ int    g_bi[Mq];
__device__ int    g_counts[2*Kc];
__device__ int    g_ccount[Mq];
__device__ int    g_candk[(size_t)Mq*CAP];
__device__ float  g_candd[(size_t)Mq*CAP];
__device__ float  g_amin[Mq];
__device__ float  g_rowsums[Mq*2];

// ---------------- helpers ----------------
__device__ __forceinline__ uint32_t smem_u32(const void* p) {
    uint32_t a;
    asm("{ .reg .u64 t; cvta.to.shared.u64 t, %1; cvt.u32.u64 %0, t; }" : "=r"(a) : "l"(p));
    return a;
}
#define SWZ(o) ((o) ^ (((o) >> 3) & 0x70))
#define MBAR_INIT(a, c) asm volatile("mbarrier.init.shared.b64 [%0], %1;" :: "r"(a), "r"(c) : "memory")
#define MBAR_EXPECT(a, b) asm volatile("mbarrier.arrive.expect_tx.shared.b64 _, [%0], %1;" :: "r"(a), "r"(b) : "memory")
#define MBAR_WAIT(a, ph) do { \
    uint32_t _m = (a), _p = (ph), _d; \
    asm volatile("{ .reg .pred p; mbarrier.try_wait.parity.acquire.cta.shared::cta.b64 p, [%1], %2; selp.b32 %0,1,0,p; }" \
        : "=r"(_d) : "r"(_m), "r"(_p) : "memory"); \
    if (!_d) { asm volatile("{ .reg .pred P1; WL_%=: mbarrier.try_wait.parity.acquire.cta.shared::cta.b64 P1, [%0], %1, 0x989680; @P1 bra.uni WD_%=; bra.uni WL_%=; WD_%=: }" \
        :: "r"(_m), "r"(_p) : "memory"); } \
} while(0)
#define BULK_G2S(dst, src, bytes, mbar) \
    asm volatile("cp.async.bulk.shared::cluster.global.mbarrier::complete_tx::bytes [%0], [%1], %2, [%3];" \
        :: "r"(dst), "l"(src), "r"(bytes), "r"(mbar) : "memory")
#define LDSM_X4(r0,r1,r2,r3,a) \
    asm volatile("ldmatrix.sync.aligned.m8n8.x4.shared.b16 {%0,%1,%2,%3}, [%4];" \
        : "=r"(r0),"=r"(r1),"=r"(r2),"=r"(r3) : "r"(a))
#define MMA16816(d,a,b) \
    asm volatile("mma.sync.aligned.m16n8k16.row.col.f32.f16.f16.f32 " \
        "{%0,%1,%2,%3}, {%4,%5,%6,%7}, {%8,%9}, {%0,%1,%2,%3};" \
        : "+f"((d)[0]),"+f"((d)[1]),"+f"((d)[2]),"+f"((d)[3]) \
        : "r"((a)[0]),"r"((a)[1]),"r"((a)[2]),"r"((a)[3]), "r"((b)[0]),"r"((b)[1]))

// ---------------- fp16 hi split (X) + scratch reset, fused ---------------
__device__ __forceinline__ uint4 pack_hi(const float* v) {
    __half2 a = __floats2half2_rn(v[0], v[1]);
    __half2 b = __floats2half2_rn(v[2], v[3]);
    __half2 c = __floats2half2_rn(v[4], v[5]);
    __half2 d = __floats2half2_rn(v[6], v[7]);
    uint4 r; r.x = *(uint32_t*)&a; r.y = *(uint32_t*)&b; r.z = *(uint32_t*)&c; r.w = *(uint32_t*)&d;
    return r;
}
__global__ void split_x_kernel(const float* __restrict__ X0, const float* __restrict__ X1) {
    // fused scratch reset (no dependency on the split writes)
    int ri = blockIdx.x * 256 + threadIdx.x;
    if (ri < 2*Kc) g_counts[ri] = 0;
    if (ri < Mq)   g_ccount[ri] = 0;

    size_t t = (size_t)blockIdx.x * 256 + threadIdx.x;   // segment id
    int m = (int)(t >> 6);
    int seg = (int)(t & 63);
    int kc = seg >> 3, s8 = seg & 7;
    const float* src = (m < Nq) ? (X0 + (size_t)m * Dd) : (X1 + (size_t)(m - Nq) * Dd);
    float v[8];
    float4 a = *(const float4*)(src + seg*8);
    float4 b = *(const float4*)(src + seg*8 + 4);
    v[0]=a.x; v[1]=a.y; v[2]=a.z; v[3]=a.w; v[4]=b.x; v[5]=b.y; v[6]=b.z; v[7]=b.w;
    size_t tile = (size_t)(m >> 7) * KIT + kc;
    uint32_t off = SWZ((uint32_t)((m & 127) * 128 + s8 * 16));
    *(uint4*)((char*)t_xhi + tile * TILE_BYTES + off) = pack_hi(v);
}

// ---------------- codebook GEMM + fused fp16-hi tile split ----------------
__global__ __launch_bounds__(256) void codebook_gemm(
    const float* __restrict__ emb, const float* __restrict__ pw,
    const float* __restrict__ pb)
{
    __shared__ float Es[16][64];
    __shared__ float Ps[16][64];
    const int tid = threadIdx.x;
    const int tx = tid & 15, ty = tid >> 4;
    const int kb = blockIdx.x * 64, db = blockIdx.y * 64;
    const int lr = tid & 63, jq = tid >> 6;
    float acc[4][4];
    #pragma unroll
    for (int i = 0; i < 4; i++)
        #pragma unroll
        for (int j = 0; j < 4; j++) acc[i][j] = 0.f;
    for (int j0 = 0; j0 < Dd; j0 += 16) {
        float4 ve = *(const float4*)(emb + (size_t)(kb+lr)*Dd + j0 + jq*4);
        Es[jq*4+0][lr]=ve.x; Es[jq*4+1][lr]=ve.y; Es[jq*4+2][lr]=ve.z; Es[jq*4+3][lr]=ve.w;
        float4 vp = *(const float4*)(pw  + (size_t)(db+lr)*Dd + j0 + jq*4);
        Ps[jq*4+0][lr]=vp.x; Ps[jq*4+1][lr]=vp.y; Ps[jq*4+2][lr]=vp.z; Ps[jq*4+3][lr]=vp.w;
        __syncthreads();
        #pragma unroll
        for (int jj = 0; jj < 16; jj++) {
            float4 a = *(const float4*)&Es[jj][ty*4];
            float4 b = *(const float4*)&Ps[jj][tx*4];
            float ar[4] = {a.x,a.y,a.z,a.w};
            float br[4] = {b.x,b.y,b.z,b.w};
            #pragma unroll
            for (int i = 0; i < 4; i++)
                #pragma unroll
                for (int j = 0; j < 4; j++)
                    acc[i][j] = fmaf(ar[i], br[j], acc[i][j]);
        }
        __syncthreads();
    }
    float bs[4];
    #pragma unroll
    for (int j = 0; j < 4; j++) bs[j] = pb[db + tx*4 + j];
    #pragma unroll
    for (int i = 0; i < 4; i++) {
        int row = kb + ty*4 + i;
        float v0 = acc[i][0] + bs[0], v1 = acc[i][1] + bs[1];
        float v2 = acc[i][2] + bs[2], v3 = acc[i][3] + bs[3];
        float* gr = g_codebook + (size_t)row * Dd + db + tx*4;
        gr[0] = v0; gr[1] = v1; gr[2] = v2; gr[3] = v3;
        // fused split_c: fp16 hi into pre-swizzled tile image
        __half2 ha = __floats2half2_rn(v0, v1);
        __half2 hb = __floats2half2_rn(v2, v3);
        uint2 pk; pk.x = *(uint32_t*)&ha; pk.y = *(uint32_t*)&hb;
        size_t tile = (size_t)(row >> 7) * KIT + (db >> 6);
        uint32_t off = SWZ((uint32_t)((row & 127) * 128 + ((db + tx*4) & 63) * 2));
        *(uint2*)((char*)t_chi + tile * TILE_BYTES + off) = pk;
    }
}

// ---------------- cb_sq ----------------
__global__ void cbsq_kernel() {
    int row  = blockIdx.x * 8 + (threadIdx.x >> 5);
    int lane = threadIdx.x & 31;
    const float* c = g_codebook + (size_t)row * Dd;
    float s = 0.f;
    for (int d = lane*4; d < Dd; d += 128) {
        float4 v = *(const float4*)(c + d);
        s += v.x*v.x + v.y*v.y + v.z*v.z + v.w*v.w;
    }
    #pragma unroll
    for (int off = 16; off; off >>= 1) s += __shfl_down_sync(0xffffffffu, s, off);
    if (lane == 0) g_cbsq[row] = s;
}

// ---------------- pass A: hi*hi MMA, X resident in SMEM -------------------
__global__ void __launch_bounds__(256, 1) argmin_mma() {
    extern __shared__ char dsm[];
    __shared__ float sCb[NTB];
    __shared__ float sD[MT][4];
    __shared__ __align__(8) unsigned long long mbar[3];   // 2 C stages + X
    uint32_t sb = (smem_u32(dsm) + 1023) & ~1023u;        // C stages base
    const uint32_t XB = sb + 2*CSTAGE_BYTES;              // resident X base
    uint32_t mb = smem_u32(mbar);

    const int tid = threadIdx.x, lane = tid & 31, wid = tid >> 5;
    const int wr = wid >> 2, wc = wid & 3;          // 2x4 warp grid, 64x64 per warp
    const int m0 = blockIdx.x * MT;
    const int r16 = lane & 15;
    const int c8  = (lane >> 4) * 8;

    float bd[8];
    #pragma unroll
    for (int s = 0; s < 8; s++) bd[s] = INFINITY;

    float acc[4][8][4];

    const size_t xblk = (size_t)(m0 >> 7) * KIT;

    auto issue = [&](int cc) {
        const int nc = cc >> 3, kc = cc & 7;
        const uint32_t st = sb + (cc & 1) * CSTAGE_BYTES;
        const uint32_t mba = mb + (cc & 1) * 8;
        MBAR_EXPECT(mba, CSTAGE_BYTES);
        const char* ch0 = (const char*)t_chi + ((size_t)(2*nc)   * KIT + kc) * TILE_BYTES;
        const char* ch1 = (const char*)t_chi + ((size_t)(2*nc+1) * KIT + kc) * TILE_BYTES;
        BULK_G2S(st,              __cvta_generic_to_global(ch0), TILE_BYTES, mba);
        BULK_G2S(st + TILE_BYTES, __cvta_generic_to_global(ch1), TILE_BYTES, mba);
    };

    if (tid == 0) {
        MBAR_INIT(mb, 1); MBAR_INIT(mb + 8, 1); MBAR_INIT(mb + 16, 1);
    }
    __syncthreads();
    if (tid == 0) {
        // resident X: 8 tiles, one barrier
        MBAR_EXPECT(mb + 16, XRES_BYTES);
        #pragma unroll
        for (int k = 0; k < KIT; k++) {
            const char* xh = (const char*)t_xhi + (xblk + k) * TILE_BYTES;
            BULK_G2S(XB + k*TILE_BYTES, __cvta_generic_to_global(xh), TILE_BYTES, mb + 16);
        }
        issue(0);
    }
    MBAR_WAIT(mb + 16, 0);    // X resident before first fragment load

    for (int cc = 0; cc < NCHUNKS; cc++) {
        const int nc = cc >> 3, kc = cc & 7;
        const int s = cc & 1;

        MBAR_WAIT(mb + s*8, (cc >> 1) & 1);
        __syncthreads();                 // all threads done with the other stage
        if (tid == 0 && cc + 1 < NCHUNKS) issue(cc + 1);

        if (kc == 0) {
            sCb[tid] = g_cbsq[nc * NTB + tid];
            #pragma unroll
            for (int f = 0; f < 4; f++)
                #pragma unroll
                for (int n = 0; n < 8; n++)
                    #pragma unroll
                    for (int v = 0; v < 4; v++) acc[f][n][v] = 0.f;
        }

        const uint32_t tb = sb + s * CSTAGE_BYTES;
        const uint32_t xk = XB + kc * TILE_BYTES;
        #pragma unroll
        for (int kb = 0; kb < 4; kb++) {
            const uint32_t colb = (uint32_t)(kb * 16 + c8) * 2;
            uint32_t ah[4][4], bh[8][2];
            #pragma unroll
            for (int f = 0; f < 4; f++) {
                uint32_t off = SWZ((uint32_t)((wr * 64 + f * 16 + r16) * 128) + colb);
                LDSM_X4(ah[f][0], ah[f][1], ah[f][2], ah[f][3], xk + off);
            }
            #pragma unroll
            for (int np = 0; np < 4; np++) {
                int brow = wc * 64 + np * 16 + r16;
                uint32_t off = (uint32_t)((brow >> 7) * TILE_BYTES)
                             + SWZ((uint32_t)((brow & 127) * 128) + colb);
                uint32_t q0, q1, q2, q3;
                LDSM_X4(q0, q1, q2, q3, tb + off);
                bh[np*2][0] = q0; bh[np*2][1] = q2; bh[np*2+1][0] = q1; bh[np*2+1][1] = q3;
            }
            #pragma unroll
            for (int f = 0; f < 4; f++)
                #pragma unroll
                for (int n = 0; n < 8; n++)
                    MMA16816(acc[f][n], ah[f], bh[n]);
        }

        if (kc == KIT - 1) {
            // epilogue: approx dist = cbsq - 2*hi.hi ; push (k, d) candidates
            #pragma unroll
            for (int f = 0; f < 4; f++) {
                int rowA = m0 + wr*64 + f*16 + (lane >> 2);
                int rowB = rowA + 8;
                #pragma unroll
                for (int n = 0; n < 8; n++) {
                    int lc = wc * 64 + n * 8 + (lane & 3) * 2;
                    int gc = nc * NTB + lc;
                    float cq0 = sCb[lc], cq1 = sCb[lc + 1];
                    float d0 = fmaf(-2.f, acc[f][n][0], cq0);
                    float d1 = fmaf(-2.f, acc[f][n][1], cq1);
                    float d2 = fmaf(-2.f, acc[f][n][2], cq0);
                    float d3 = fmaf(-2.f, acc[f][n][3], cq1);
                    if (d0 < bd[f] + MARGIN) {
                        int p = atomicAdd(&g_ccount[rowA], 1);
                        if (p < CAP) { g_candk[(size_t)rowA*CAP + p] = gc;   g_candd[(size_t)rowA*CAP + p] = d0; }
                        if (d0 < bd[f]) bd[f] = d0;
                    }
                    if (d1 < bd[f] + MARGIN) {
                        int p = atomicAdd(&g_ccount[rowA], 1);
                        if (p < CAP) { g_candk[(size_t)rowA*CAP + p] = gc+1; g_candd[(size_t)rowA*CAP + p] = d1; }
                        if (d1 < bd[f]) bd[f] = d1;
                    }
                    if (d2 < bd[f+4] + MARGIN) {
                        int p = atomicAdd(&g_ccount[rowB], 1);
                        if (p < CAP) { g_candk[(size_t)rowB*CAP + p] = gc;   g_candd[(size_t)rowB*CAP + p] = d2; }
                        if (d2 < bd[f+4]) bd[f+4] = d2;
                    }
                    if (d3 < bd[f+4] + MARGIN) {
                        int p = atomicAdd(&g_ccount[rowB], 1);
                        if (p < CAP) { g_candk[(size_t)rowB*CAP + p] = gc+1; g_candd[(size_t)rowB*CAP + p] = d3; }
                        if (d3 < bd[f+4]) bd[f+4] = d3;
                    }
                }
            }
        }
    }

    // final per-row approx minimum (for candidate filtering)
    #pragma unroll
    for (int s = 0; s < 8; s++) {
        #pragma unroll
        for (int x = 1; x <= 2; x <<= 1)
            bd[s] = fminf(bd[s], __shfl_xor_sync(0xffffffffu, bd[s], x));
        int row = wr * 64 + (s & 3) * 16 + (lane >> 2) + ((s >= 4) ? 8 : 0);
        if ((lane & 3) == 0) sD[row][wc] = bd[s];
    }
    __syncthreads();
    if (tid < MT) {
        float a = fminf(fminf(sD[tid][0], sD[tid][1]), fminf(sD[tid][2], sD[tid][3]));
        g_amin[m0 + tid] = a;
    }
}

// ---------------- filtered exact fp32 rescore ----------------
__global__ void __launch_bounds__(128) rescore_kernel(
    const float* __restrict__ X0, const float* __restrict__ X1)
{
    const int m = blockIdx.x;
    const int tid = threadIdx.x, lane = tid & 31, w = tid >> 5;  // 4 warps
    __shared__ float sx[Dd];
    __shared__ float wbD[4];
    __shared__ int   wbK[4];

    const float* x = (m < Nq) ? (X0 + (size_t)m*Dd) : (X1 + (size_t)(m-Nq)*Dd);
    for (int i = tid; i < Dd; i += 128) sx[i] = x[i];
    __syncthreads();

    const float thr = g_amin[m] + MARGIN;
    int cnt = g_ccount[m]; if (cnt > CAP) cnt = CAP;
    float best = INFINITY; int bk = 0x7fffffff;
    for (int c = w; c < cnt; c += 4) {
        float da = g_candd[(size_t)m*CAP + c];
        if (da > thr) continue;                       // filtered out
        int k = g_candk[(size_t)m*CAP + c];
        const float* cb = g_codebook + (size_t)k * Dd;
        float s = 0.f;
        for (int j = lane; j < Dd; j += 32) s = fmaf(sx[j], cb[j], s);
        #pragma unroll
        for (int o = 16; o; o >>= 1) s += __shfl_xor_sync(0xffffffffu, s, o);
        float d = fmaf(-2.f, s, g_cbsq[k]);
        if (d < best || (d == best && k < bk)) { best = d; bk = k; }
    }
    if (lane == 0) { wbD[w] = best; wbK[w] = bk; }
    __syncthreads();
    if (tid == 0) {
        float B = wbD[0]; int K = wbK[0];
        #pragma unroll
        for (int i = 1; i < 4; i++)
            if (wbD[i] < B || (wbD[i] == B && wbK[i] < K)) { B = wbD[i]; K = wbK[i]; }
        g_bi[m] = K;
    }
}

// ---------------- gather + per-row MSE partials ----------------
__global__ void gather_kernel(const float* __restrict__ X0,
                              const float* __restrict__ X1,
                              float* __restrict__ out)
{
    const int m = blockIdx.x;
    const int tid = threadIdx.x;   // 128
    __shared__ float wsum[4][2];

    const int idx = g_bi[m];
    if (tid == 0) {
        int src = (m < Nq) ? 0 : 1;
        atomicAdd(&g_counts[src*Kc + idx], 1);
    }
    const float* q = g_codebook + (size_t)idx * Dd;
    const float *x, *o; float* op;
    if (m < Nq) { x = X0 + (size_t)m*Dd; o = X1 + (size_t)m*Dd; op = out + (size_t)m*Dd; }
    else { int mr = m - Nq;
           x = X1 + (size_t)mr*Dd; o = X0 + (size_t)mr*Dd; op = out + (size_t)(Nq+mr)*Dd; }

    float4 qv = *(const float4*)(q + tid*4);
    float4 xv = *(const float4*)(x + tid*4);
    float4 ov = *(const float4*)(o + tid*4);
    float dx0 = qv.x - xv.x, dx1 = qv.y - xv.y, dx2 = qv.z - xv.z, dx3 = qv.w - xv.w;
    float4 w = {xv.x + dx0, xv.y + dx1, xv.z + dx2, xv.w + dx3};
    *(float4*)(op + tid*4) = w;

    float sA = dx0*dx0 + dx1*dx1 + dx2*dx2 + dx3*dx3;
    float e0 = qv.x - ov.x, e1 = qv.y - ov.y, e2 = qv.z - ov.z, e3 = qv.w - ov.w;
    float sB = e0*e0 + e1*e1 + e2*e2 + e3*e3;
    #pragma unroll
    for (int off = 16; off; off >>= 1) {
        sA += __shfl_down_sync(0xffffffffu, sA, off);
        sB += __shfl_down_sync(0xffffffffu, sB, off);
    }
    int warp = tid >> 5, lane = tid & 31;
    if (lane == 0) { wsum[warp][0] = sA; wsum[warp][1] = sB; }
    __syncthreads();
    if (tid == 0) {
        g_rowsums[2*m]   = wsum[0][0] + wsum[1][0] + wsum[2][0] + wsum[3][0];
        g_rowsums[2*m+1] = wsum[0][1] + wsum[1][1] + wsum[2][1] + wsum[3][1];
    }
}

// ---------------- losses ----------------
__global__ void loss_kernel(float* __restrict__ out) {
    const int t = threadIdx.x;
    __shared__ double red[4][256];
    double es = 0, csr = 0, er = 0, crs = 0;
    for (int m = t; m < Nq; m += 256)      { es  += (double)g_rowsums[2*m]; csr += (double)g_rowsums[2*m+1]; }
    for (int m = Nq + t; m < Mq; m += 256) { er  += (double)g_rowsums[2*m]; crs += (double)g_rowsums[2*m+1]; }
    red[0][t]=es; red[1][t]=csr; red[2][t]=er; red[3][t]=crs;
    __syncthreads();
    for (int off = 128; off; off >>= 1) {
        if (t < off) {
            red[0][t]+=red[0][t+off]; red[1][t]+=red[1][t+off];
            red[2][t]+=red[2][t+off]; red[3][t]+=red[3][t+off];
        }
        __syncthreads();
    }
    if (t == 0) {
        const double nd = (double)Nq * (double)Dd;
        double Es = red[0][0]/nd, Csr = red[1][0]/nd, Er = red[2][0]/nd, Crs = red[3][0]/nd;
        out[(size_t)2*Nq*Dd + 0] = (float)(0.5 * Es);
        double fwd = Er + Es + 0.5*Crs + 0.5*Csr;
        out[(size_t)2*Nq*Dd + 1] = (float)(0.5*Er + 0.25*fwd);
    }
}

// ---------------- perplexity ----------------
__global__ void perp_kernel(float* __restrict__ out) {
    const int src = blockIdx.x;
    const int t = threadIdx.x;
    __shared__ float red[256];
    float h = 0.f;
    for (int k = t; k < Kc; k += 256) {
        float p = (float)g_counts[src*Kc + k] * (1.0f/(float)Nq);
        h += p * logf(p + 1e-10f);
    }
    red[t] = h;
    __syncthreads();
    for (int off = 128; off; off >>= 1) {
        if (t < off) red[t] += red[t+off];
        __syncthreads();
    }
    if (t == 0) out[(size_t)2*Nq*Dd + 2 + src] = expf(-red[0]);
}

// ---------------- launcher ----------------
extern "C" void kernel_launch(void* const* d_in, const int* in_sizes, int n_in,
                              void* d_out, int out_size)
{
    const float* scRNA = (const float*)d_in[0];
    const float* ribo  = (const float*)d_in[1];
    const float* emb   = (const float*)d_in[2];
    const float* pw    = (const float*)d_in[3];
    const float* pb    = (const float*)d_in[4];
    float* out = (float*)d_out;

    cudaFuncSetAttribute(argmin_mma, cudaFuncAttributeMaxDynamicSharedMemorySize, DSM_BYTES);

    split_x_kernel<<<(int)(((size_t)Mq*Dd/8)/256), 256>>>(scRNA, ribo);   // + scratch reset
    codebook_gemm<<<dim3(Kc/64, Dd/64), 256>>>(emb, pw, pb);              // + split_c fused
    cbsq_kernel<<<Kc/8, 256>>>();
    argmin_mma<<<Mq/MT, 256, DSM_BYTES>>>();                              // launch #4 -> profiled
    rescore_kernel<<<Mq, 128>>>(scRNA, ribo);
    gather_kernel<<<Mq, 128>>>(scRNA, ribo, out);
    loss_kernel<<<1, 256>>>(out);
    perp_kernel<<<2, 256>>>(out);
}

// round 13
// speedup vs baseline: 1.4144x; 1.2239x over previous
#include <cuda_runtime.h>
#include <cuda_fp16.h>
#include <math.h>
#include <stdint.h>

#define Nq 8192
#define Kc 8192
#define Dd 512
#define Mq (2*Nq)

// ---- mma-argmin tiling ----
#define MT 128                 // queries per CTA
#define NTB 256                // codes per N-chunk (CTA tile 128x256)
#define NCB (Kc/NTB)           // 32
#define KCH 64                 // halfs per K chunk
#define KIT (Dd/KCH)           // 8
#define NCHUNKS (NCB*KIT)      // 256 pipeline steps
#define TILE_BYTES 16384       // one [128][64] half tile, swizzled
#define CSTAGE_BYTES 32768     // 2 codebook tiles per chunk
#define XRES_BYTES (KIT*TILE_BYTES)   // 128KB resident X
#define DSM_BYTES (1024 + 2*CSTAGE_BYTES + XRES_BYTES)
#define CAP 512                // candidate slots per row
#define MARGIN 0.125f          // >= 2x deterministic hi*hi error bound

// ---------------- device scratch ----------------
__device__ float  g_codebook[Kc*Dd];
__device__ __align__(16) __half t_chi[(size_t)Kc*Dd];
__device__ __align__(16) __half t_xhi[(size_t)Mq*Dd];
__device__ float  g_cbsq[Kc];
__device__ int    g_bi[Mq];
__device__ int    g_counts[2*Kc];
__device__ int    g_ccount[Mq];
__device__ int    g_candk[(size_t)Mq*CAP];
__device__ float  g_candd[(size_t)Mq*CAP];
__device__ float  g_amin[Mq];
__device__ float  g_rowsums[Mq*2];

// ---------------- helpers ----------------
__device__ __forceinline__ uint32_t smem_u32(const void* p) {
    uint32_t a;
    asm("{ .reg .u64 t; cvta.to.shared.u64 t, %1; cvt.u32.u64 %0, t; }" : "=r"(a) : "l"(p));
    return a;
}
#define SWZ(o) ((o) ^ (((o) >> 3) & 0x70))
#define MBAR_INIT(a, c) asm volatile("mbarrier.init.shared.b64 [%0], %1;" :: "r"(a), "r"(c) : "memory")
#define MBAR_EXPECT(a, b) asm volatile("mbarrier.arrive.expect_tx.shared.b64 _, [%0], %1;" :: "r"(a), "r"(b) : "memory")
#define MBAR_WAIT(a, ph) do { \
    uint32_t _m = (a), _p = (ph), _d; \
    asm volatile("{ .reg .pred p; mbarrier.try_wait.parity.acquire.cta.shared::cta.b64 p, [%1], %2; selp.b32 %0,1,0,p; }" \
        : "=r"(_d) : "r"(_m), "r"(_p) : "memory"); \
    if (!_d) { asm volatile("{ .reg .pred P1; WL_%=: mbarrier.try_wait.parity.acquire.cta.shared::cta.b64 P1, [%0], %1, 0x989680; @P1 bra.uni WD_%=; bra.uni WL_%=; WD_%=: }" \
        :: "r"(_m), "r"(_p) : "memory"); } \
} while(0)
#define BULK_G2S(dst, src, bytes, mbar) \
    asm volatile("cp.async.bulk.shared::cluster.global.mbarrier::complete_tx::bytes [%0], [%1], %2, [%3];" \
        :: "r"(dst), "l"(src), "r"(bytes), "r"(mbar) : "memory")
#define LDSM_X4(r0,r1,r2,r3,a) \
    asm volatile("ldmatrix.sync.aligned.m8n8.x4.shared.b16 {%0,%1,%2,%3}, [%4];" \
        : "=r"(r0),"=r"(r1),"=r"(r2),"=r"(r3) : "r"(a))
#define MMA16816(d,a,b) \
    asm volatile("mma.sync.aligned.m16n8k16.row.col.f32.f16.f16.f32 " \
        "{%0,%1,%2,%3}, {%4,%5,%6,%7}, {%8,%9}, {%0,%1,%2,%3};" \
        : "+f"((d)[0]),"+f"((d)[1]),"+f"((d)[2]),"+f"((d)[3]) \
        : "r"((a)[0]),"r"((a)[1]),"r"((a)[2]),"r"((a)[3]), "r"((b)[0]),"r"((b)[1]))

// ---------------- fp16 hi split (X) + scratch reset, fused ---------------
__device__ __forceinline__ uint4 pack_hi(const float* v) {
    __half2 a = __floats2half2_rn(v[0], v[1]);
    __half2 b = __floats2half2_rn(v[2], v[3]);
    __half2 c = __floats2half2_rn(v[4], v[5]);
    __half2 d = __floats2half2_rn(v[6], v[7]);
    uint4 r; r.x = *(uint32_t*)&a; r.y = *(uint32_t*)&b; r.z = *(uint32_t*)&c; r.w = *(uint32_t*)&d;
    return r;
}
__global__ void split_x_kernel(const float* __restrict__ X0, const float* __restrict__ X1) {
    int ri = blockIdx.x * 256 + threadIdx.x;
    if (ri < 2*Kc) g_counts[ri] = 0;
    if (ri < Mq)   g_ccount[ri] = 0;

    size_t t = (size_t)blockIdx.x * 256 + threadIdx.x;   // segment id
    int m = (int)(t >> 6);
    int seg = (int)(t & 63);
    int kc = seg >> 3, s8 = seg & 7;
    const float* src = (m < Nq) ? (X0 + (size_t)m * Dd) : (X1 + (size_t)(m - Nq) * Dd);
    float v[8];
    float4 a = *(const float4*)(src + seg*8);
    float4 b = *(const float4*)(src + seg*8 + 4);
    v[0]=a.x; v[1]=a.y; v[2]=a.z; v[3]=a.w; v[4]=b.x; v[5]=b.y; v[6]=b.z; v[7]=b.w;
    size_t tile = (size_t)(m >> 7) * KIT + kc;
    uint32_t off = SWZ((uint32_t)((m & 127) * 128 + s8 * 16));
    *(uint4*)((char*)t_xhi + tile * TILE_BYTES + off) = pack_hi(v);
}

// ---------------- codebook GEMM + fused fp16-hi tile split ----------------
__global__ __launch_bounds__(256) void codebook_gemm(
    const float* __restrict__ emb, const float* __restrict__ pw,
    const float* __restrict__ pb)
{
    __shared__ float Es[16][64];
    __shared__ float Ps[16][64];
    const int tid = threadIdx.x;
    const int tx = tid & 15, ty = tid >> 4;
    const int kb = blockIdx.x * 64, db = blockIdx.y * 64;
    const int lr = tid & 63, jq = tid >> 6;
    float acc[4][4];
    #pragma unroll
    for (int i = 0; i < 4; i++)
        #pragma unroll
        for (int j = 0; j < 4; j++) acc[i][j] = 0.f;
    for (int j0 = 0; j0 < Dd; j0 += 16) {
        float4 ve = *(const float4*)(emb + (size_t)(kb+lr)*Dd + j0 + jq*4);
        Es[jq*4+0][lr]=ve.x; Es[jq*4+1][lr]=ve.y; Es[jq*4+2][lr]=ve.z; Es[jq*4+3][lr]=ve.w;
        float4 vp = *(const float4*)(pw  + (size_t)(db+lr)*Dd + j0 + jq*4);
        Ps[jq*4+0][lr]=vp.x; Ps[jq*4+1][lr]=vp.y; Ps[jq*4+2][lr]=vp.z; Ps[jq*4+3][lr]=vp.w;
        __syncthreads();
        #pragma unroll
        for (int jj = 0; jj < 16; jj++) {
            float4 a = *(const float4*)&Es[jj][ty*4];
            float4 b = *(const float4*)&Ps[jj][tx*4];
            float ar[4] = {a.x,a.y,a.z,a.w};
            float br[4] = {b.x,b.y,b.z,b.w};
            #pragma unroll
            for (int i = 0; i < 4; i++)
                #pragma unroll
                for (int j = 0; j < 4; j++)
                    acc[i][j] = fmaf(ar[i], br[j], acc[i][j]);
        }
        __syncthreads();
    }
    float bs[4];
    #pragma unroll
    for (int j = 0; j < 4; j++) bs[j] = pb[db + tx*4 + j];
    #pragma unroll
    for (int i = 0; i < 4; i++) {
        int row = kb + ty*4 + i;
        float v0 = acc[i][0] + bs[0], v1 = acc[i][1] + bs[1];
        float v2 = acc[i][2] + bs[2], v3 = acc[i][3] + bs[3];
        float* gr = g_codebook + (size_t)row * Dd + db + tx*4;
        gr[0] = v0; gr[1] = v1; gr[2] = v2; gr[3] = v3;
        __half2 ha = __floats2half2_rn(v0, v1);
        __half2 hb = __floats2half2_rn(v2, v3);
        uint2 pk; pk.x = *(uint32_t*)&ha; pk.y = *(uint32_t*)&hb;
        size_t tile = (size_t)(row >> 7) * KIT + (db >> 6);
        uint32_t off = SWZ((uint32_t)((row & 127) * 128 + ((db + tx*4) & 63) * 2));
        *(uint2*)((char*)t_chi + tile * TILE_BYTES + off) = pk;
    }
}

// ---------------- cb_sq ----------------
__global__ void cbsq_kernel() {
    int row  = blockIdx.x * 8 + (threadIdx.x >> 5);
    int lane = threadIdx.x & 31;
    const float* c = g_codebook + (size_t)row * Dd;
    float s = 0.f;
    for (int d = lane*4; d < Dd; d += 128) {
        float4 v = *(const float4*)(c + d);
        s += v.x*v.x + v.y*v.y + v.z*v.z + v.w*v.w;
    }
    #pragma unroll
    for (int off = 16; off; off >>= 1) s += __shfl_down_sync(0xffffffffu, s, off);
    if (lane == 0) g_cbsq[row] = s;
}

// ---------------- pass A: hi*hi MMA, X resident, 512 threads --------------
__global__ void __launch_bounds__(512, 1) argmin_mma() {
    extern __shared__ char dsm[];
    __shared__ float sCb[NTB];
    __shared__ float sD[MT][4];
    __shared__ __align__(8) unsigned long long mbar[3];   // 2 C stages + X
    uint32_t sb = (smem_u32(dsm) + 1023) & ~1023u;        // C stages base
    const uint32_t XB = sb + 2*CSTAGE_BYTES;              // resident X base
    uint32_t mb = smem_u32(mbar);

    const int tid = threadIdx.x, lane = tid & 31, wid = tid >> 5;
    const int wr = wid >> 2, wc = wid & 3;          // 4x4 warp grid, 32x64 per warp
    const int m0 = blockIdx.x * MT;
    const int r16 = lane & 15;
    const int c8  = (lane >> 4) * 8;

    float bd[4];
    #pragma unroll
    for (int s = 0; s < 4; s++) bd[s] = INFINITY;

    float acc[2][8][4];    // 64 regs

    const size_t xblk = (size_t)(m0 >> 7) * KIT;

    auto issue = [&](int cc) {
        const int nc = cc >> 3, kc = cc & 7;
        const uint32_t st = sb + (cc & 1) * CSTAGE_BYTES;
        const uint32_t mba = mb + (cc & 1) * 8;
        MBAR_EXPECT(mba, CSTAGE_BYTES);
        const char* ch0 = (const char*)t_chi + ((size_t)(2*nc)   * KIT + kc) * TILE_BYTES;
        const char* ch1 = (const char*)t_chi + ((size_t)(2*nc+1) * KIT + kc) * TILE_BYTES;
        BULK_G2S(st,              __cvta_generic_to_global(ch0), TILE_BYTES, mba);
        BULK_G2S(st + TILE_BYTES, __cvta_generic_to_global(ch1), TILE_BYTES, mba);
    };

    if (tid == 0) {
        MBAR_INIT(mb, 1); MBAR_INIT(mb + 8, 1); MBAR_INIT(mb + 16, 1);
    }
    __syncthreads();
    if (tid == 0) {
        MBAR_EXPECT(mb + 16, XRES_BYTES);
        #pragma unroll
        for (int k = 0; k < KIT; k++) {
            const char* xh = (const char*)t_xhi + (xblk + k) * TILE_BYTES;
            BULK_G2S(XB + k*TILE_BYTES, __cvta_generic_to_global(xh), TILE_BYTES, mb + 16);
        }
        issue(0);
    }
    MBAR_WAIT(mb + 16, 0);    // X resident before first fragment load

    for (int cc = 0; cc < NCHUNKS; cc++) {
        const int nc = cc >> 3, kc = cc & 7;
        const int s = cc & 1;

        MBAR_WAIT(mb + s*8, (cc >> 1) & 1);
        __syncthreads();                 // all threads done with the other stage
        if (tid == 0 && cc + 1 < NCHUNKS) issue(cc + 1);

        if (kc == 0) {
            if (tid < NTB) sCb[tid] = g_cbsq[nc * NTB + tid];
            #pragma unroll
            for (int f = 0; f < 2; f++)
                #pragma unroll
                for (int n = 0; n < 8; n++)
                    #pragma unroll
                    for (int v = 0; v < 4; v++) acc[f][n][v] = 0.f;
        }

        const uint32_t tb = sb + s * CSTAGE_BYTES;
        const uint32_t xk = XB + kc * TILE_BYTES;
        #pragma unroll
        for (int kb = 0; kb < 4; kb++) {
            const uint32_t colb = (uint32_t)(kb * 16 + c8) * 2;
            uint32_t ah[2][4], bh[8][2];
            #pragma unroll
            for (int f = 0; f < 2; f++) {
                uint32_t off = SWZ((uint32_t)((wr * 32 + f * 16 + r16) * 128) + colb);
                LDSM_X4(ah[f][0], ah[f][1], ah[f][2], ah[f][3], xk + off);
            }
            #pragma unroll
            for (int np = 0; np < 4; np++) {
                int brow = wc * 64 + np * 16 + r16;
                uint32_t off = (uint32_t)((brow >> 7) * TILE_BYTES)
                             + SWZ((uint32_t)((brow & 127) * 128) + colb);
                uint32_t q0, q1, q2, q3;
                LDSM_X4(q0, q1, q2, q3, tb + off);
                bh[np*2][0] = q0; bh[np*2][1] = q2; bh[np*2+1][0] = q1; bh[np*2+1][1] = q3;
            }
            #pragma unroll
            for (int f = 0; f < 2; f++)
                #pragma unroll
                for (int n = 0; n < 8; n++)
                    MMA16816(acc[f][n], ah[f], bh[n]);
        }

        if (kc == KIT - 1) {
            // epilogue: approx dist = cbsq - 2*hi.hi ; push (k, d) candidates
            #pragma unroll
            for (int f = 0; f < 2; f++) {
                int rowA = m0 + wr*32 + f*16 + (lane >> 2);
                int rowB = rowA + 8;
                #pragma unroll
                for (int n = 0; n < 8; n++) {
                    int lc = wc * 64 + n * 8 + (lane & 3) * 2;
                    int gc = nc * NTB + lc;
                    float cq0 = sCb[lc], cq1 = sCb[lc + 1];
                    float d0 = fmaf(-2.f, acc[f][n][0], cq0);
                    float d1 = fmaf(-2.f, acc[f][n][1], cq1);
                    float d2 = fmaf(-2.f, acc[f][n][2], cq0);
                    float d3 = fmaf(-2.f, acc[f][n][3], cq1);
                    if (d0 < bd[f] + MARGIN) {
                        int p = atomicAdd(&g_ccount[rowA], 1);
                        if (p < CAP) { g_candk[(size_t)rowA*CAP + p] = gc;   g_candd[(size_t)rowA*CAP + p] = d0; }
                        if (d0 < bd[f]) bd[f] = d0;
                    }
                    if (d1 < bd[f] + MARGIN) {
                        int p = atomicAdd(&g_ccount[rowA], 1);
                        if (p < CAP) { g_candk[(size_t)rowA*CAP + p] = gc+1; g_candd[(size_t)rowA*CAP + p] = d1; }
                        if (d1 < bd[f]) bd[f] = d1;
                    }
                    if (d2 < bd[f+2] + MARGIN) {
                        int p = atomicAdd(&g_ccount[rowB], 1);
                        if (p < CAP) { g_candk[(size_t)rowB*CAP + p] = gc;   g_candd[(size_t)rowB*CAP + p] = d2; }
                        if (d2 < bd[f+2]) bd[f+2] = d2;
                    }
                    if (d3 < bd[f+2] + MARGIN) {
                        int p = atomicAdd(&g_ccount[rowB], 1);
                        if (p < CAP) { g_candk[(size_t)rowB*CAP + p] = gc+1; g_candd[(size_t)rowB*CAP + p] = d3; }
                        if (d3 < bd[f+2]) bd[f+2] = d3;
                    }
                }
            }
        }
    }

    // final per-row approx minimum (for candidate filtering)
    #pragma unroll
    for (int s = 0; s < 4; s++) {
        #pragma unroll
        for (int x = 1; x <= 2; x <<= 1)
            bd[s] = fminf(bd[s], __shfl_xor_sync(0xffffffffu, bd[s], x));
        int row = wr * 32 + (s & 1) * 16 + (lane >> 2) + ((s >= 2) ? 8 : 0);
        if ((lane & 3) == 0) sD[row][wc] = bd[s];
    }
    __syncthreads();
    if (tid < MT) {
        float a = fminf(fminf(sD[tid][0], sD[tid][1]), fminf(sD[tid][2], sD[tid][3]));
        g_amin[m0 + tid] = a;
    }
}

// ---------------- filtered exact fp32 rescore ----------------
__global__ void __launch_bounds__(128) rescore_kernel(
    const float* __restrict__ X0, const float* __restrict__ X1)
{
    const int m = blockIdx.x;
    const int tid = threadIdx.x, lane = tid & 31, w = tid >> 5;  // 4 warps
    __shared__ float sx[Dd];
    __shared__ float wbD[4];
    __shared__ int   wbK[4];

    const float* x = (m < Nq) ? (X0 + (size_t)m*Dd) : (X1 + (size_t)(m-Nq)*Dd);
    for (int i = tid; i < Dd; i += 128) sx[i] = x[i];
    __syncthreads();

    const float thr = g_amin[m] + MARGIN;
    int cnt = g_ccount[m]; if (cnt > CAP) cnt = CAP;
    float best = INFINITY; int bk = 0x7fffffff;
    for (int c = w; c < cnt; c += 4) {
        float da = g_candd[(size_t)m*CAP + c];
        if (da > thr) continue;                       // filtered out
        int k = g_candk[(size_t)m*CAP + c];
        const float* cb = g_codebook + (size_t)k * Dd;
        float s = 0.f;
        for (int j = lane; j < Dd; j += 32) s = fmaf(sx[j], cb[j], s);
        #pragma unroll
        for (int o = 16; o; o >>= 1) s += __shfl_xor_sync(0xffffffffu, s, o);
        float d = fmaf(-2.f, s, g_cbsq[k]);
        if (d < best || (d == best && k < bk)) { best = d; bk = k; }
    }
    if (lane == 0) { wbD[w] = best; wbK[w] = bk; }
    __syncthreads();
    if (tid == 0) {
        float B = wbD[0]; int K = wbK[0];
        #pragma unroll
        for (int i = 1; i < 4; i++)
            if (wbD[i] < B || (wbD[i] == B && wbK[i] < K)) { B = wbD[i]; K = wbK[i]; }
        g_bi[m] = K;
    }
}

// ---------------- gather + per-row MSE partials ----------------
__global__ void gather_kernel(const float* __restrict__ X0,
                              const float* __restrict__ X1,
                              float* __restrict__ out)
{
    const int m = blockIdx.x;
    const int tid = threadIdx.x;   // 128
    __shared__ float wsum[4][2];

    const int idx = g_bi[m];
    if (tid == 0) {
        int src = (m < Nq) ? 0 : 1;
        atomicAdd(&g_counts[src*Kc + idx], 1);
    }
    const float* q = g_codebook + (size_t)idx * Dd;
    const float *x, *o; float* op;
    if (m < Nq) { x = X0 + (size_t)m*Dd; o = X1 + (size_t)m*Dd; op = out + (size_t)m*Dd; }
    else { int mr = m - Nq;
           x = X1 + (size_t)mr*Dd; o = X0 + (size_t)mr*Dd; op = out + (size_t)(Nq+mr)*Dd; }

    float4 qv = *(const float4*)(q + tid*4);
    float4 xv = *(const float4*)(x + tid*4);
    float4 ov = *(const float4*)(o + tid*4);
    float dx0 = qv.x - xv.x, dx1 = qv.y - xv.y, dx2 = qv.z - xv.z, dx3 = qv.w - xv.w;
    float4 w = {xv.x + dx0, xv.y + dx1, xv.z + dx2, xv.w + dx3};
    *(float4*)(op + tid*4) = w;

    float sA = dx0*dx0 + dx1*dx1 + dx2*dx2 + dx3*dx3;
    float e0 = qv.x - ov.x, e1 = qv.y - ov.y, e2 = qv.z - ov.z, e3 = qv.w - ov.w;
    float sB = e0*e0 + e1*e1 + e2*e2 + e3*e3;
    #pragma unroll
    for (int off = 16; off; off >>= 1) {
        sA += __shfl_down_sync(0xffffffffu, sA, off);
        sB += __shfl_down_sync(0xffffffffu, sB, off);
    }
    int warp = tid >> 5, lane = tid & 31;
    if (lane == 0) { wsum[warp][0] = sA; wsum[warp][1] = sB; }
    __syncthreads();
    if (tid == 0) {
        g_rowsums[2*m]   = wsum[0][0] + wsum[1][0] + wsum[2][0] + wsum[3][0];
        g_rowsums[2*m+1] = wsum[0][1] + wsum[1][1] + wsum[2][1] + wsum[3][1];
    }
}

// ---------------- losses ----------------
__global__ void loss_kernel(float* __restrict__ out) {
    const int t = threadIdx.x;
    __shared__ double red[4][256];
    double es = 0, csr = 0, er = 0, crs = 0;
    for (int m = t; m < Nq; m += 256)      { es  += (double)g_rowsums[2*m]; csr += (double)g_rowsums[2*m+1]; }
    for (int m = Nq + t; m < Mq; m += 256) { er  += (double)g_rowsums[2*m]; crs += (double)g_rowsums[2*m+1]; }
    red[0][t]=es; red[1][t]=csr; red[2][t]=er; red[3][t]=crs;
    __syncthreads();
    for (int off = 128; off; off >>= 1) {
        if (t < off) {
            red[0][t]+=red[0][t+off]; red[1][t]+=red[1][t+off];
            red[2][t]+=red[2][t+off]; red[3][t]+=red[3][t+off];
        }
        __syncthreads();
    }
    if (t == 0) {
        const double nd = (double)Nq * (double)Dd;
        double Es = red[0][0]/nd, Csr = red[1][0]/nd, Er = red[2][0]/nd, Crs = red[3][0]/nd;
        out[(size_t)2*Nq*Dd + 0] = (float)(0.5 * Es);
        double fwd = Er + Es + 0.5*Crs + 0.5*Csr;
        out[(size_t)2*Nq*Dd + 1] = (float)(0.5*Er + 0.25*fwd);
    }
}

// ---------------- perplexity ----------------
__global__ void perp_kernel(float* __restrict__ out) {
    const int src = blockIdx.x;
    const int t = threadIdx.x;
    __shared__ float red[256];
    float h = 0.f;
    for (int k = t; k < Kc; k += 256) {
        float p = (float)g_counts[src*Kc + k] * (1.0f/(float)Nq);
        h += p * logf(p + 1e-10f);
    }
    red[t] = h;
    __syncthreads();
    for (int off = 128; off; off >>= 1) {
        if (t < off) red[t] += red[t+off];
        __syncthreads();
    }
    if (t == 0) out[(size_t)2*Nq*Dd + 2 + src] = expf(-red[0]);
}

// ---------------- launcher ----------------
extern "C" void kernel_launch(void* const* d_in, const int* in_sizes, int n_in,
                              void* d_out, int out_size)
{
    const float* scRNA = (const float*)d_in[0];
    const float* ribo  = (const float*)d_in[1];
    const float* emb   = (const float*)d_in[2];
    const float* pw    = (const float*)d_in[3];
    const float* pb    = (const float*)d_in[4];
    float* out = (float*)d_out;

    cudaFuncSetAttribute(argmin_mma, cudaFuncAttributeMaxDynamicSharedMemorySize, DSM_BYTES);

    split_x_kernel<<<(int)(((size_t)Mq*Dd/8)/256), 256>>>(scRNA, ribo);   // + scratch reset
    codebook_gemm<<<dim3(Kc/64, Dd/64), 256>>>(emb, pw, pb);              // + split_c fused
    cbsq_kernel<<<Kc/8, 256>>>();
    argmin_mma<<<Mq/MT, 512, DSM_BYTES>>>();                              // 16 warps/SM
    rescore_kernel<<<Mq, 128>>>(scRNA, ribo);
    gather_kernel<<<Mq, 128>>>(scRNA, ribo, out);
    loss_kernel<<<1, 256>>>(out);
    perp_kernel<<<2, 256>>>(out);
}

// round 14
// speedup vs baseline: 1.5634x; 1.1053x over previous
#include <cuda_runtime.h>
#include <cuda_fp16.h>
#include <math.h>
#include <stdint.h>

#define Nq 8192
#define Kc 8192
#define Dd 512
#define Mq (2*Nq)

// ---- mma-argmin tiling ----
#define MT 128                 // queries per CTA
#define NTB 256                // codes per N-chunk (CTA tile 128x256)
#define NCB (Kc/NTB)           // 32
#define KCH 64                 // halfs per K chunk
#define KIT (Dd/KCH)           // 8
#define NCHUNKS (NCB*KIT)      // 256 pipeline steps
#define TILE_BYTES 16384       // one [128][64] half tile, swizzled
#define CSTAGE_BYTES 32768     // 2 codebook tiles per chunk
#define XRES_BYTES (KIT*TILE_BYTES)   // 128KB resident X
#define DSM_BYTES (1024 + 2*CSTAGE_BYTES + XRES_BYTES)
#define CAP 512                // candidate slots per row
#define MARGIN 0.125f          // >= 2x deterministic hi*hi error bound

// ---------------- device scratch ----------------
__device__ float  g_codebook[Kc*Dd];
__device__ __align__(16) __half t_chi[(size_t)Kc*Dd];
__device__ __align__(16) __half t_xhi[(size_t)Mq*Dd];
__device__ float  g_cbsq[Kc];
__device__ int    g_bi[Mq];
__device__ int    g_counts[2*Kc];
__device__ int    g_ccount[Mq];
__device__ int    g_candk[(size_t)Mq*CAP];
__device__ float  g_candd[(size_t)Mq*CAP];
__device__ float  g_amin[Mq];
__device__ float  g_rowsums[Mq*2];

// ---------------- helpers ----------------
__device__ __forceinline__ uint32_t smem_u32(const void* p) {
    uint32_t a;
    asm("{ .reg .u64 t; cvta.to.shared.u64 t, %1; cvt.u32.u64 %0, t; }" : "=r"(a) : "l"(p));
    return a;
}
#define SWZ(o) ((o) ^ (((o) >> 3) & 0x70))
#define MBAR_INIT(a, c) asm volatile("mbarrier.init.shared.b64 [%0], %1;" :: "r"(a), "r"(c) : "memory")
#define MBAR_EXPECT(a, b) asm volatile("mbarrier.arrive.expect_tx.shared.b64 _, [%0], %1;" :: "r"(a), "r"(b) : "memory")
#define MBAR_WAIT(a, ph) do { \
    uint32_t _m = (a), _p = (ph), _d; \
    asm volatile("{ .reg .pred p; mbarrier.try_wait.parity.acquire.cta.shared::cta.b64 p, [%1], %2; selp.b32 %0,1,0,p; }" \
        : "=r"(_d) : "r"(_m), "r"(_p) : "memory"); \
    if (!_d) { asm volatile("{ .reg .pred P1; WL_%=: mbarrier.try_wait.parity.acquire.cta.shared::cta.b64 P1, [%0], %1, 0x989680; @P1 bra.uni WD_%=; bra.uni WL_%=; WD_%=: }" \
        :: "r"(_m), "r"(_p) : "memory"); } \
} while(0)
#define BULK_G2S(dst, src, bytes, mbar) \
    asm volatile("cp.async.bulk.shared::cluster.global.mbarrier::complete_tx::bytes [%0], [%1], %2, [%3];" \
        :: "r"(dst), "l"(src), "r"(bytes), "r"(mbar) : "memory")
#define LDSM_X4(r0,r1,r2,r3,a) \
    asm volatile("ldmatrix.sync.aligned.m8n8.x4.shared.b16 {%0,%1,%2,%3}, [%4];" \
        : "=r"(r0),"=r"(r1),"=r"(r2),"=r"(r3) : "r"(a))
#define MMA16816(d,a,b) \
    asm volatile("mma.sync.aligned.m16n8k16.row.col.f32.f16.f16.f32 " \
        "{%0,%1,%2,%3}, {%4,%5,%6,%7}, {%8,%9}, {%0,%1,%2,%3};" \
        : "+f"((d)[0]),"+f"((d)[1]),"+f"((d)[2]),"+f"((d)[3]) \
        : "r"((a)[0]),"r"((a)[1]),"r"((a)[2]),"r"((a)[3]), "r"((b)[0]),"r"((b)[1]))

// ---------------- fp16 hi split (X) + scratch reset, fused ---------------
__device__ __forceinline__ uint4 pack_hi(const float* v) {
    __half2 a = __floats2half2_rn(v[0], v[1]);
    __half2 b = __floats2half2_rn(v[2], v[3]);
    __half2 c = __floats2half2_rn(v[4], v[5]);
    __half2 d = __floats2half2_rn(v[6], v[7]);
    uint4 r; r.x = *(uint32_t*)&a; r.y = *(uint32_t*)&b; r.z = *(uint32_t*)&c; r.w = *(uint32_t*)&d;
    return r;
}
__global__ void split_x_kernel(const float* __restrict__ X0, const float* __restrict__ X1) {
    int ri = blockIdx.x * 256 + threadIdx.x;
    if (ri < 2*Kc) g_counts[ri] = 0;
    if (ri < Mq)   g_ccount[ri] = 0;

    size_t t = (size_t)blockIdx.x * 256 + threadIdx.x;   // segment id
    int m = (int)(t >> 6);
    int seg = (int)(t & 63);
    int kc = seg >> 3, s8 = seg & 7;
    const float* src = (m < Nq) ? (X0 + (size_t)m * Dd) : (X1 + (size_t)(m - Nq) * Dd);
    float v[8];
    float4 a = *(const float4*)(src + seg*8);
    float4 b = *(const float4*)(src + seg*8 + 4);
    v[0]=a.x; v[1]=a.y; v[2]=a.z; v[3]=a.w; v[4]=b.x; v[5]=b.y; v[6]=b.z; v[7]=b.w;
    size_t tile = (size_t)(m >> 7) * KIT + kc;
    uint32_t off = SWZ((uint32_t)((m & 127) * 128 + s8 * 16));
    *(uint4*)((char*)t_xhi + tile * TILE_BYTES + off) = pack_hi(v);
}

// ---------------- codebook GEMM + fused fp16-hi tile split ----------------
__global__ __launch_bounds__(256) void codebook_gemm(
    const float* __restrict__ emb, const float* __restrict__ pw,
    const float* __restrict__ pb)
{
    __shared__ float Es[16][64];
    __shared__ float Ps[16][64];
    const int tid = threadIdx.x;
    const int tx = tid & 15, ty = tid >> 4;
    const int kb = blockIdx.x * 64, db = blockIdx.y * 64;
    const int lr = tid & 63, jq = tid >> 6;
    float acc[4][4];
    #pragma unroll
    for (int i = 0; i < 4; i++)
        #pragma unroll
        for (int j = 0; j < 4; j++) acc[i][j] = 0.f;
    for (int j0 = 0; j0 < Dd; j0 += 16) {
        float4 ve = *(const float4*)(emb + (size_t)(kb+lr)*Dd + j0 + jq*4);
        Es[jq*4+0][lr]=ve.x; Es[jq*4+1][lr]=ve.y; Es[jq*4+2][lr]=ve.z; Es[jq*4+3][lr]=ve.w;
        float4 vp = *(const float4*)(pw  + (size_t)(db+lr)*Dd + j0 + jq*4);
        Ps[jq*4+0][lr]=vp.x; Ps[jq*4+1][lr]=vp.y; Ps[jq*4+2][lr]=vp.z; Ps[jq*4+3][lr]=vp.w;
        __syncthreads();
        #pragma unroll
        for (int jj = 0; jj < 16; jj++) {
            float4 a = *(const float4*)&Es[jj][ty*4];
            float4 b = *(const float4*)&Ps[jj][tx*4];
            float ar[4] = {a.x,a.y,a.z,a.w};
            float br[4] = {b.x,b.y,b.z,b.w};
            #pragma unroll
            for (int i = 0; i < 4; i++)
                #pragma unroll
                for (int j = 0; j < 4; j++)
                    acc[i][j] = fmaf(ar[i], br[j], acc[i][j]);
        }
        __syncthreads();
    }
    float bs[4];
    #pragma unroll
    for (int j = 0; j < 4; j++) bs[j] = pb[db + tx*4 + j];
    #pragma unroll
    for (int i = 0; i < 4; i++) {
        int row = kb + ty*4 + i;
        float v0 = acc[i][0] + bs[0], v1 = acc[i][1] + bs[1];
        float v2 = acc[i][2] + bs[2], v3 = acc[i][3] + bs[3];
        float* gr = g_codebook + (size_t)row * Dd + db + tx*4;
        gr[0] = v0; gr[1] = v1; gr[2] = v2; gr[3] = v3;
        __half2 ha = __floats2half2_rn(v0, v1);
        __half2 hb = __floats2half2_rn(v2, v3);
        uint2 pk; pk.x = *(uint32_t*)&ha; pk.y = *(uint32_t*)&hb;
        size_t tile = (size_t)(row >> 7) * KIT + (db >> 6);
        uint32_t off = SWZ((uint32_t)((row & 127) * 128 + ((db + tx*4) & 63) * 2));
        *(uint2*)((char*)t_chi + tile * TILE_BYTES + off) = pk;
    }
}

// ---------------- cb_sq ----------------
__global__ void cbsq_kernel() {
    int row  = blockIdx.x * 8 + (threadIdx.x >> 5);
    int lane = threadIdx.x & 31;
    const float* c = g_codebook + (size_t)row * Dd;
    float s = 0.f;
    for (int d = lane*4; d < Dd; d += 128) {
        float4 v = *(const float4*)(c + d);
        s += v.x*v.x + v.y*v.y + v.z*v.z + v.w*v.w;
    }
    #pragma unroll
    for (int off = 16; off; off >>= 1) s += __shfl_down_sync(0xffffffffu, s, off);
    if (lane == 0) g_cbsq[row] = s;
}

// ---------------- pass A: hi*hi MMA, X resident, 1024 threads -------------
__global__ void __launch_bounds__(1024, 1) argmin_mma() {
    extern __shared__ char dsm[];
    __shared__ float sCb[NTB];
    __shared__ float sD[MT][4];
    __shared__ __align__(8) unsigned long long mbar[3];   // 2 C stages + X
    uint32_t sb = (smem_u32(dsm) + 1023) & ~1023u;        // C stages base
    const uint32_t XB = sb + 2*CSTAGE_BYTES;              // resident X base
    uint32_t mb = smem_u32(mbar);

    const int tid = threadIdx.x, lane = tid & 31, wid = tid >> 5;
    const int wr = wid >> 2, wc = wid & 3;          // 8x4 warp grid, 16x64 per warp
    const int m0 = blockIdx.x * MT;
    const int r16 = lane & 15;
    const int c8  = (lane >> 4) * 8;

    float bd[2];
    bd[0] = INFINITY; bd[1] = INFINITY;

    float acc[8][4];    // 32 regs

    const size_t xblk = (size_t)(m0 >> 7) * KIT;

    auto issue = [&](int cc) {
        const int nc = cc >> 3, kc = cc & 7;
        const uint32_t st = sb + (cc & 1) * CSTAGE_BYTES;
        const uint32_t mba = mb + (cc & 1) * 8;
        MBAR_EXPECT(mba, CSTAGE_BYTES);
        const char* ch0 = (const char*)t_chi + ((size_t)(2*nc)   * KIT + kc) * TILE_BYTES;
        const char* ch1 = (const char*)t_chi + ((size_t)(2*nc+1) * KIT + kc) * TILE_BYTES;
        BULK_G2S(st,              __cvta_generic_to_global(ch0), TILE_BYTES, mba);
        BULK_G2S(st + TILE_BYTES, __cvta_generic_to_global(ch1), TILE_BYTES, mba);
    };

    if (tid == 0) {
        MBAR_INIT(mb, 1); MBAR_INIT(mb + 8, 1); MBAR_INIT(mb + 16, 1);
    }
    __syncthreads();
    if (tid == 0) {
        MBAR_EXPECT(mb + 16, XRES_BYTES);
        #pragma unroll
        for (int k = 0; k < KIT; k++) {
            const char* xh = (const char*)t_xhi + (xblk + k) * TILE_BYTES;
            BULK_G2S(XB + k*TILE_BYTES, __cvta_generic_to_global(xh), TILE_BYTES, mb + 16);
        }
        issue(0);
    }
    MBAR_WAIT(mb + 16, 0);    // X resident before first fragment load

    for (int cc = 0; cc < NCHUNKS; cc++) {
        const int nc = cc >> 3, kc = cc & 7;
        const int s = cc & 1;

        MBAR_WAIT(mb + s*8, (cc >> 1) & 1);
        __syncthreads();                 // all threads done with the other stage
        if (tid == 0 && cc + 1 < NCHUNKS) issue(cc + 1);

        if (kc == 0) {
            if (tid < NTB) sCb[tid] = g_cbsq[nc * NTB + tid];
            #pragma unroll
            for (int n = 0; n < 8; n++)
                #pragma unroll
                for (int v = 0; v < 4; v++) acc[n][v] = 0.f;
        }

        const uint32_t tb = sb + s * CSTAGE_BYTES;
        const uint32_t xk = XB + kc * TILE_BYTES;
        #pragma unroll
        for (int kb = 0; kb < 4; kb++) {
            const uint32_t colb = (uint32_t)(kb * 16 + c8) * 2;
            uint32_t ah[4], bh[8][2];
            {
                uint32_t off = SWZ((uint32_t)((wr * 16 + r16) * 128) + colb);
                LDSM_X4(ah[0], ah[1], ah[2], ah[3], xk + off);
            }
            #pragma unroll
            for (int np = 0; np < 4; np++) {
                int brow = wc * 64 + np * 16 + r16;
                uint32_t off = (uint32_t)((brow >> 7) * TILE_BYTES)
                             + SWZ((uint32_t)((brow & 127) * 128) + colb);
                uint32_t q0, q1, q2, q3;
                LDSM_X4(q0, q1, q2, q3, tb + off);
                bh[np*2][0] = q0; bh[np*2][1] = q2; bh[np*2+1][0] = q1; bh[np*2+1][1] = q3;
            }
            #pragma unroll
            for (int n = 0; n < 8; n++)
                MMA16816(acc[n], ah, bh[n]);
        }

        if (kc == KIT - 1) {
            // epilogue: approx dist = cbsq - 2*hi.hi ; push (k, d) candidates
            int rowA = m0 + wr*16 + (lane >> 2);
            int rowB = rowA + 8;
            #pragma unroll
            for (int n = 0; n < 8; n++) {
                int lc = wc * 64 + n * 8 + (lane & 3) * 2;
                int gc = nc * NTB + lc;
                float cq0 = sCb[lc], cq1 = sCb[lc + 1];
                float d0 = fmaf(-2.f, acc[n][0], cq0);
                float d1 = fmaf(-2.f, acc[n][1], cq1);
                float d2 = fmaf(-2.f, acc[n][2], cq0);
                float d3 = fmaf(-2.f, acc[n][3], cq1);
                if (d0 < bd[0] + MARGIN) {
                    int p = atomicAdd(&g_ccount[rowA], 1);
                    if (p < CAP) { g_candk[(size_t)rowA*CAP + p] = gc;   g_candd[(size_t)rowA*CAP + p] = d0; }
                    if (d0 < bd[0]) bd[0] = d0;
                }
                if (d1 < bd[0] + MARGIN) {
                    int p = atomicAdd(&g_ccount[rowA], 1);
                    if (p < CAP) { g_candk[(size_t)rowA*CAP + p] = gc+1; g_candd[(size_t)rowA*CAP + p] = d1; }
                    if (d1 < bd[0]) bd[0] = d1;
                }
                if (d2 < bd[1] + MARGIN) {
                    int p = atomicAdd(&g_ccount[rowB], 1);
                    if (p < CAP) { g_candk[(size_t)rowB*CAP + p] = gc;   g_candd[(size_t)rowB*CAP + p] = d2; }
                    if (d2 < bd[1]) bd[1] = d2;
                }
                if (d3 < bd[1] + MARGIN) {
                    int p = atomicAdd(&g_ccount[rowB], 1);
                    if (p < CAP) { g_candk[(size_t)rowB*CAP + p] = gc+1; g_candd[(size_t)rowB*CAP + p] = d3; }
                    if (d3 < bd[1]) bd[1] = d3;
                }
            }
        }
    }

    // final per-row approx minimum (for candidate filtering)
    #pragma unroll
    for (int s = 0; s < 2; s++) {
        #pragma unroll
        for (int x = 1; x <= 2; x <<= 1)
            bd[s] = fminf(bd[s], __shfl_xor_sync(0xffffffffu, bd[s], x));
        int row = wr * 16 + (lane >> 2) + s * 8;
        if ((lane & 3) == 0) sD[row][wc] = bd[s];
    }
    __syncthreads();
    if (tid < MT) {
        float a = fminf(fminf(sD[tid][0], sD[tid][1]), fminf(sD[tid][2], sD[tid][3]));
        g_amin[m0 + tid] = a;
    }
}

// ---------------- filtered exact fp32 rescore ----------------
__global__ void __launch_bounds__(128) rescore_kernel(
    const float* __restrict__ X0, const float* __restrict__ X1)
{
    const int m = blockIdx.x;
    const int tid = threadIdx.x, lane = tid & 31, w = tid >> 5;  // 4 warps
    __shared__ float sx[Dd];
    __shared__ float wbD[4];
    __shared__ int   wbK[4];

    const float* x = (m < Nq) ? (X0 + (size_t)m*Dd) : (X1 + (size_t)(m-Nq)*Dd);
    for (int i = tid; i < Dd; i += 128) sx[i] = x[i];
    __syncthreads();

    const float thr = g_amin[m] + MARGIN;
    int cnt = g_ccount[m]; if (cnt > CAP) cnt = CAP;
    float best = INFINITY; int bk = 0x7fffffff;
    for (int c = w; c < cnt; c += 4) {
        float da = g_candd[(size_t)m*CAP + c];
        if (da > thr) continue;                       // filtered out
        int k = g_candk[(size_t)m*CAP + c];
        const float* cb = g_codebook + (size_t)k * Dd;
        float s = 0.f;
        for (int j = lane; j < Dd; j += 32) s = fmaf(sx[j], cb[j], s);
        #pragma unroll
        for (int o = 16; o; o >>= 1) s += __shfl_xor_sync(0xffffffffu, s, o);
        float d = fmaf(-2.f, s, g_cbsq[k]);
        if (d < best || (d == best && k < bk)) { best = d; bk = k; }
    }
    if (lane == 0) { wbD[w] = best; wbK[w] = bk; }
    __syncthreads();
    if (tid == 0) {
        float B = wbD[0]; int K = wbK[0];
        #pragma unroll
        for (int i = 1; i < 4; i++)
            if (wbD[i] < B || (wbD[i] == B && wbK[i] < K)) { B = wbD[i]; K = wbK[i]; }
        g_bi[m] = K;
    }
}

// ---------------- gather + per-row MSE partials ----------------
__global__ void gather_kernel(const float* __restrict__ X0,
                              const float* __restrict__ X1,
                              float* __restrict__ out)
{
    const int m = blockIdx.x;
    const int tid = threadIdx.x;   // 128
    __shared__ float wsum[4][2];

    const int idx = g_bi[m];
    if (tid == 0) {
        int src = (m < Nq) ? 0 : 1;
        atomicAdd(&g_counts[src*Kc + idx], 1);
    }
    const float* q = g_codebook + (size_t)idx * Dd;
    const float *x, *o; float* op;
    if (m < Nq) { x = X0 + (size_t)m*Dd; o = X1 + (size_t)m*Dd; op = out + (size_t)m*Dd; }
    else { int mr = m - Nq;
           x = X1 + (size_t)mr*Dd; o = X0 + (size_t)mr*Dd; op = out + (size_t)(Nq+mr)*Dd; }

    float4 qv = *(const float4*)(q + tid*4);
    float4 xv = *(const float4*)(x + tid*4);
    float4 ov = *(const float4*)(o + tid*4);
    float dx0 = qv.x - xv.x, dx1 = qv.y - xv.y, dx2 = qv.z - xv.z, dx3 = qv.w - xv.w;
    float4 w = {xv.x + dx0, xv.y + dx1, xv.z + dx2, xv.w + dx3};
    *(float4*)(op + tid*4) = w;

    float sA = dx0*dx0 + dx1*dx1 + dx2*dx2 + dx3*dx3;
    float e0 = qv.x - ov.x, e1 = qv.y - ov.y, e2 = qv.z - ov.z, e3 = qv.w - ov.w;
    float sB = e0*e0 + e1*e1 + e2*e2 + e3*e3;
    #pragma unroll
    for (int off = 16; off; off >>= 1) {
        sA += __shfl_down_sync(0xffffffffu, sA, off);
        sB += __shfl_down_sync(0xffffffffu, sB, off);
    }
    int warp = tid >> 5, lane = tid & 31;
    if (lane == 0) { wsum[warp][0] = sA; wsum[warp][1] = sB; }
    __syncthreads();
    if (tid == 0) {
        g_rowsums[2*m]   = wsum[0][0] + wsum[1][0] + wsum[2][0] + wsum[3][0];
        g_rowsums[2*m+1] = wsum[0][1] + wsum[1][1] + wsum[2][1] + wsum[3][1];
    }
}

// ---------------- losses ----------------
__global__ void loss_kernel(float* __restrict__ out) {
    const int t = threadIdx.x;
    __shared__ double red[4][256];
    double es = 0, csr = 0, er = 0, crs = 0;
    for (int m = t; m < Nq; m += 256)      { es  += (double)g_rowsums[2*m]; csr += (double)g_rowsums[2*m+1]; }
    for (int m = Nq + t; m < Mq; m += 256) { er  += (double)g_rowsums[2*m]; crs += (double)g_rowsums[2*m+1]; }
    red[0][t]=es; red[1][t]=csr; red[2][t]=er; red[3][t]=crs;
    __syncthreads();
    for (int off = 128; off; off >>= 1) {
        if (t < off) {
            red[0][t]+=red[0][t+off]; red[1][t]+=red[1][t+off];
            red[2][t]+=red[2][t+off]; red[3][t]+=red[3][t+off];
        }
        __syncthreads();
    }
    if (t == 0) {
        const double nd = (double)Nq * (double)Dd;
        double Es = red[0][0]/nd, Csr = red[1][0]/nd, Er = red[2][0]/nd, Crs = red[3][0]/nd;
        out[(size_t)2*Nq*Dd + 0] = (float)(0.5 * Es);
        double fwd = Er + Es + 0.5*Crs + 0.5*Csr;
        out[(size_t)2*Nq*Dd + 1] = (float)(0.5*Er + 0.25*fwd);
    }
}

// ---------------- perplexity ----------------
__global__ void perp_kernel(float* __restrict__ out) {
    const int src = blockIdx.x;
    const int t = threadIdx.x;
    __shared__ float red[256];
    float h = 0.f;
    for (int k = t; k < Kc; k += 256) {
        float p = (float)g_counts[src*Kc + k] * (1.0f/(float)Nq);
        h += p * logf(p + 1e-10f);
    }
    red[t] = h;
    __syncthreads();
    for (int off = 128; off; off >>= 1) {
        if (t < off) red[t] += red[t+off];
        __syncthreads();
    }
    if (t == 0) out[(size_t)2*Nq*Dd + 2 + src] = expf(-red[0]);
}

// ---------------- launcher ----------------
extern "C" void kernel_launch(void* const* d_in, const int* in_sizes, int n_in,
                              void* d_out, int out_size)
{
    const float* scRNA = (const float*)d_in[0];
    const float* ribo  = (const float*)d_in[1];
    const float* emb   = (const float*)d_in[2];
    const float* pw    = (const float*)d_in[3];
    const float* pb    = (const float*)d_in[4];
    float* out = (float*)d_out;

    cudaFuncSetAttribute(argmin_mma, cudaFuncAttributeMaxDynamicSharedMemorySize, DSM_BYTES);

    split_x_kernel<<<(int)(((size_t)Mq*Dd/8)/256), 256>>>(scRNA, ribo);   // + scratch reset
    codebook_gemm<<<dim3(Kc/64, Dd/64), 256>>>(emb, pw, pb);              // + split_c fused
    cbsq_kernel<<<Kc/8, 256>>>();
    argmin_mma<<<Mq/MT, 1024, DSM_BYTES>>>();                             // 32 warps/SM
    rescore_kernel<<<Mq, 128>>>(scRNA, ribo);
    gather_kernel<<<Mq, 128>>>(scRNA, ribo, out);
    loss_kernel<<<1, 256>>>(out);
    perp_kernel<<<2, 256>>>(out);
}